// round 1
// baseline (speedup 1.0000x reference)
#include <cuda_runtime.h>

// ---------------- problem constants (fixed shapes) ----------------
#define NNODES 16384
#define NEDGES 65536
#define MAXF   4096

// ---------------- scratch (device globals; no allocation) ----------------
__device__ float g_h[(size_t)NNODES * MAXF];   // GEMM output  (pre-aggregation)
__device__ float g_a[(size_t)NNODES * MAXF];   // aggregated conv output (pre-relu)
__device__ float g_deg[NNODES];
__device__ float g_dinv[NNODES];
__device__ float g_self[NNODES];
__device__ int   g_count[NNODES];
__device__ int   g_rowptr[NNODES + 1];
__device__ int   g_cursor[NNODES];
__device__ int   g_csrc[NEDGES];
__device__ float g_cw[NEDGES];

// ---------------- graph prep ----------------
__global__ void k_prep_zero() {
    int i = blockIdx.x * blockDim.x + threadIdx.x;
    if (i < NNODES) { g_deg[i] = 0.f; g_count[i] = 0; }
}

__global__ void k_prep_edges(const int* __restrict__ src, const int* __restrict__ dst,
                             const float* __restrict__ ew) {
    int e = blockIdx.x * blockDim.x + threadIdx.x;
    if (e < NEDGES) {
        atomicAdd(&g_deg[dst[e]], ew[e]);
        atomicAdd(&g_count[dst[e]], 1);
    }
}

__global__ void k_prep_node() {
    int i = blockIdx.x * blockDim.x + threadIdx.x;
    if (i < NNODES) {
        float d = g_deg[i] + 1.0f;
        g_dinv[i] = rsqrtf(d);
        g_self[i] = 1.0f / d;
    }
}

// single block, 1024 threads: exclusive scan of g_count -> g_rowptr / g_cursor
__global__ void k_scan() {
    int tid = threadIdx.x;
    int c[16];
    int tot = 0;
#pragma unroll
    for (int j = 0; j < 16; j++) { c[j] = tot; tot += g_count[tid * 16 + j]; }
    __shared__ int s[1024];
    s[tid] = tot;
    __syncthreads();
    int mytot = tot;
    for (int off = 1; off < 1024; off <<= 1) {
        int v = (tid >= off) ? s[tid - off] : 0;
        __syncthreads();
        s[tid] += v;
        __syncthreads();
    }
    int incl = s[tid];
    int excl = incl - mytot;
#pragma unroll
    for (int j = 0; j < 16; j++) {
        int v = excl + c[j];
        g_rowptr[tid * 16 + j] = v;
        g_cursor[tid * 16 + j] = v;
    }
    if (tid == 1023) g_rowptr[NNODES] = incl;
}

__global__ void k_fill(const int* __restrict__ src, const int* __restrict__ dst,
                       const float* __restrict__ ew) {
    int e = blockIdx.x * blockDim.x + threadIdx.x;
    if (e < NEDGES) {
        int s = src[e], d = dst[e];
        float norm = g_dinv[s] * ew[e] * g_dinv[d];
        int p = atomicAdd(&g_cursor[d], 1);
        g_csrc[p] = s;
        g_cw[p] = norm;
    }
}

// ---------------- aggregation (CSR gather, float4) ----------------
// out[n] = self[n]*h[n] + bias + sum_{in-edges} w * h[src]
__global__ void k_agg(const float* __restrict__ h, const float* __restrict__ bias,
                      float* __restrict__ out, int F) {
    int n  = blockIdx.y;
    int f4 = blockIdx.x * blockDim.x + threadIdx.x;
    int F4 = F >> 2;
    if (f4 >= F4) return;
    const float4* hrow = (const float4*)(h + (size_t)n * F);
    float4 hv = hrow[f4];
    float  sc = g_self[n];
    float4 bb = ((const float4*)bias)[f4];
    float4 acc;
    acc.x = sc * hv.x + bb.x;
    acc.y = sc * hv.y + bb.y;
    acc.z = sc * hv.z + bb.z;
    acc.w = sc * hv.w + bb.w;
    int beg = g_rowptr[n], end = g_rowptr[n + 1];
    for (int j = beg; j < end; j++) {
        int   s = g_csrc[j];
        float w = g_cw[j];
        float4 sv = ((const float4*)(h + (size_t)s * F))[f4];
        acc.x += w * sv.x;
        acc.y += w * sv.y;
        acc.z += w * sv.z;
        acc.w += w * sv.w;
    }
    ((float4*)(out + (size_t)n * F))[f4] = acc;
}

// ---------------- fp32 SIMT GEMM: C = op(A) @ B (+bias) ----------------
// A: [M,K] row-major (op = optional relu on load), B: [K,N] row-major.
// 128x128 block tile, BK=16, 256 threads, 8x8 per thread (split 4+4 layout).
#define BM 128
#define BN 128
#define BK 16

template <bool RELU, bool BIAS>
__global__ __launch_bounds__(256) void k_gemm(const float* __restrict__ A,
                                              const float* __restrict__ B,
                                              const float* __restrict__ bias,
                                              float* __restrict__ C,
                                              int M, int N, int K) {
    __shared__ __align__(16) float As[BK][BM + 4];
    __shared__ __align__(16) float Bs[BK][BN];

    int tid = threadIdx.x;
    int tx  = tid & 15;   // N direction (16 threads)
    int ty  = tid >> 4;   // M direction (16 threads)
    int m0  = blockIdx.y * BM;
    int n0  = blockIdx.x * BN;

    int arow = tid >> 2;          // 0..63
    int acol = (tid & 3) << 2;    // 0,4,8,12
    int brow = tid >> 5;          // 0..7
    int bcol = (tid & 31) << 2;   // 0..124

    float acc[8][8];
#pragma unroll
    for (int i = 0; i < 8; i++)
#pragma unroll
        for (int j = 0; j < 8; j++) acc[i][j] = 0.f;

    for (int k0 = 0; k0 < K; k0 += BK) {
        // ---- load A tile (128 x 16), store transposed As[k][m]
#pragma unroll
        for (int r = 0; r < 2; r++) {
            int m = m0 + arow + r * 64;
            float4 v = *(const float4*)(A + (size_t)m * K + k0 + acol);
            if (RELU) {
                v.x = fmaxf(v.x, 0.f); v.y = fmaxf(v.y, 0.f);
                v.z = fmaxf(v.z, 0.f); v.w = fmaxf(v.w, 0.f);
            }
            As[acol + 0][arow + r * 64] = v.x;
            As[acol + 1][arow + r * 64] = v.y;
            As[acol + 2][arow + r * 64] = v.z;
            As[acol + 3][arow + r * 64] = v.w;
        }
        // ---- load B tile (16 x 128)
#pragma unroll
        for (int r = 0; r < 2; r++) {
            int kk = brow + r * 8;
            int n  = n0 + bcol;
            float4 v;
            if (n + 3 < N) {
                v = *(const float4*)(B + (size_t)(k0 + kk) * N + n);
            } else {
                v.x = (n + 0 < N) ? B[(size_t)(k0 + kk) * N + n + 0] : 0.f;
                v.y = (n + 1 < N) ? B[(size_t)(k0 + kk) * N + n + 1] : 0.f;
                v.z = (n + 2 < N) ? B[(size_t)(k0 + kk) * N + n + 2] : 0.f;
                v.w = (n + 3 < N) ? B[(size_t)(k0 + kk) * N + n + 3] : 0.f;
            }
            *(float4*)&Bs[kk][bcol] = v;
        }
        __syncthreads();

#pragma unroll
        for (int kk = 0; kk < BK; kk++) {
            float ra[8], rb[8];
            *(float4*)&ra[0] = *(const float4*)&As[kk][ty * 4];
            *(float4*)&ra[4] = *(const float4*)&As[kk][64 + ty * 4];
            *(float4*)&rb[0] = *(const float4*)&Bs[kk][tx * 4];
            *(float4*)&rb[4] = *(const float4*)&Bs[kk][64 + tx * 4];
#pragma unroll
            for (int i = 0; i < 8; i++)
#pragma unroll
                for (int j = 0; j < 8; j++) acc[i][j] = fmaf(ra[i], rb[j], acc[i][j]);
        }
        __syncthreads();
    }

    // ---- epilogue: C rows {m0 + ih*64 + ty*4 + i}, cols {n0 + jh*64 + tx*4 + j}
#pragma unroll
    for (int ih = 0; ih < 2; ih++) {
#pragma unroll
        for (int i = 0; i < 4; i++) {
            int m = m0 + ih * 64 + ty * 4 + i;
#pragma unroll
            for (int jh = 0; jh < 2; jh++) {
                int n = n0 + jh * 64 + tx * 4;
                float v0 = acc[ih * 4 + i][jh * 4 + 0];
                float v1 = acc[ih * 4 + i][jh * 4 + 1];
                float v2 = acc[ih * 4 + i][jh * 4 + 2];
                float v3 = acc[ih * 4 + i][jh * 4 + 3];
                if (BIAS) {
                    v0 += bias[min(n + 0, N - 1)];
                    v1 += bias[min(n + 1, N - 1)];
                    v2 += bias[min(n + 2, N - 1)];
                    v3 += bias[min(n + 3, N - 1)];
                }
                float* cp = C + (size_t)m * N + n;
                if (n + 3 < N) {
                    float4 v = make_float4(v0, v1, v2, v3);
                    *(float4*)cp = v;
                } else {
                    if (n + 0 < N) cp[0] = v0;
                    if (n + 1 < N) cp[1] = v1;
                    if (n + 2 < N) cp[2] = v2;
                    if (n + 3 < N) cp[3] = v3;
                }
            }
        }
    }
}

// ---------------- host orchestration ----------------
static inline void launch_gemm(bool relu, bool biasflag,
                               const float* A, const float* B, const float* bias,
                               float* C, int M, int N, int K) {
    dim3 grid((N + BN - 1) / BN, M / BM);
    dim3 block(256);
    if (relu) {
        if (biasflag) k_gemm<true, true><<<grid, block>>>(A, B, bias, C, M, N, K);
        else          k_gemm<true, false><<<grid, block>>>(A, B, bias, C, M, N, K);
    } else {
        if (biasflag) k_gemm<false, true><<<grid, block>>>(A, B, bias, C, M, N, K);
        else          k_gemm<false, false><<<grid, block>>>(A, B, bias, C, M, N, K);
    }
}

static inline void launch_agg(const float* h, const float* bias, float* out, int F) {
    int F4 = F >> 2;
    dim3 grid((F4 + 255) / 256, NNODES);
    k_agg<<<grid, 256>>>(h, bias, out, F);
}

extern "C" void kernel_launch(void* const* d_in, const int* in_sizes, int n_in,
                              void* d_out, int out_size) {
    const float* x    = (const float*)d_in[0];
    const int*   esrc = (const int*)d_in[1];
    const int*   edst = (const int*)d_in[2];
    const float* ew   = (const float*)d_in[3];
    const float* W1 = (const float*)d_in[4];
    const float* b1 = (const float*)d_in[5];
    const float* W2 = (const float*)d_in[6];
    const float* b2 = (const float*)d_in[7];
    const float* W3 = (const float*)d_in[8];
    const float* b3 = (const float*)d_in[9];
    const float* W4 = (const float*)d_in[10];
    const float* b4 = (const float*)d_in[11];
    const float* Wout = (const float*)d_in[12];
    const float* bout = (const float*)d_in[13];
    float* out = (float*)d_out;

    float* hbuf = nullptr;
    float* abuf = nullptr;
    cudaGetSymbolAddress((void**)&hbuf, g_h);
    cudaGetSymbolAddress((void**)&abuf, g_a);

    // ---- graph prep (degree, norms, CSR by dst)
    k_prep_zero<<<NNODES / 256, 256>>>();
    k_prep_edges<<<NEDGES / 256, 256>>>(esrc, edst, ew);
    k_prep_node<<<NNODES / 256, 256>>>();
    k_scan<<<1, 1024>>>();
    k_fill<<<NEDGES / 256, 256>>>(esrc, edst, ew);

    const int M = NNODES;

    // Layer 1: x[16384,512] @ W1 -> [.,1024]; agg; (relu fused into next gemm)
    launch_gemm(false, false, x, W1, nullptr, hbuf, M, 1024, 512);
    launch_agg(hbuf, b1, abuf, 1024);

    // Layer 2: relu(a) @ W2 -> [.,2048]
    launch_gemm(true, false, abuf, W2, nullptr, hbuf, M, 2048, 1024);
    launch_agg(hbuf, b2, abuf, 2048);

    // Layer 3: relu(a) @ W3 -> [.,4096]
    launch_gemm(true, false, abuf, W3, nullptr, hbuf, M, 4096, 2048);
    launch_agg(hbuf, b3, abuf, 4096);

    // Layer 4: relu(a) @ W4 -> [.,2048]
    launch_gemm(true, false, abuf, W4, nullptr, hbuf, M, 2048, 4096);
    launch_agg(hbuf, b4, abuf, 2048);

    // Output: relu(a) @ Wout + bout -> [.,1000]
    launch_gemm(true, true, abuf, Wout, bout, out, M, 1000, 2048);
}

// round 5
// speedup vs baseline: 2.4558x; 2.4558x over previous
#include <cuda_runtime.h>
#include <cuda_bf16.h>
#include <cstdint>

#define NNODES 16384
#define NEDGES 65536
#define MAXF   4096

typedef __nv_bfloat16 bf16;

// ---------------- scratch (device globals; no allocation) ----------------
__device__ float g_h[(size_t)NNODES * MAXF];          // f32 GEMM output
__device__ bf16  g_ahi[(size_t)NNODES * MAXF];        // split activations (hi)
__device__ bf16  g_alo[(size_t)NNODES * MAXF];        // split activations (lo)
__device__ bf16  g_wth[(size_t)4096 * 2048];          // transposed weights hi [Npad,K]
__device__ bf16  g_wtl[(size_t)4096 * 2048];          // transposed weights lo
__device__ float g_deg[NNODES];
__device__ float g_dinv[NNODES];
__device__ float g_self[NNODES];
__device__ int   g_count[NNODES];
__device__ int   g_rowptr[NNODES + 1];
__device__ int   g_cursor[NNODES];
__device__ int   g_csrc[NEDGES];
__device__ float g_cw[NEDGES];

// ---------------- PTX helpers (baseline PTX only; no tcgen05) ----------------
__device__ __forceinline__ uint32_t smem_u32(const void* p) {
    uint32_t a;
    asm("{ .reg .u64 t; cvta.to.shared.u64 t, %1; cvt.u32.u64 %0, t; }" : "=r"(a) : "l"(p));
    return a;
}
__device__ __forceinline__ void cp16(uint32_t s, const void* g) {
    asm volatile("cp.async.cg.shared.global [%0], [%1], 16;" :: "r"(s), "l"(g));
}
__device__ __forceinline__ void cp_commit() { asm volatile("cp.async.commit_group;" ::: "memory"); }
template <int N>
__device__ __forceinline__ void cp_wait() { asm volatile("cp.async.wait_group %0;" :: "n"(N) : "memory"); }

__device__ __forceinline__ void ldsm4(uint32_t* r, uint32_t addr) {
    asm volatile("ldmatrix.sync.aligned.m8n8.x4.shared.b16 {%0,%1,%2,%3}, [%4];"
                 : "=r"(r[0]), "=r"(r[1]), "=r"(r[2]), "=r"(r[3]) : "r"(addr));
}
__device__ __forceinline__ void mma16816(float* d, const uint32_t* a, const uint32_t* b) {
    asm volatile(
        "mma.sync.aligned.m16n8k16.row.col.f32.bf16.bf16.f32 "
        "{%0,%1,%2,%3}, {%4,%5,%6,%7}, {%8,%9}, {%0,%1,%2,%3};"
        : "+f"(d[0]), "+f"(d[1]), "+f"(d[2]), "+f"(d[3])
        : "r"(a[0]), "r"(a[1]), "r"(a[2]), "r"(a[3]), "r"(b[0]), "r"(b[1]));
}

// ---------------- graph prep ----------------
__global__ void k_prep_zero() {
    int i = blockIdx.x * blockDim.x + threadIdx.x;
    if (i < NNODES) { g_deg[i] = 0.f; g_count[i] = 0; }
}
__global__ void k_prep_edges(const int* __restrict__ src, const int* __restrict__ dst,
                             const float* __restrict__ ew) {
    int e = blockIdx.x * blockDim.x + threadIdx.x;
    if (e < NEDGES) {
        atomicAdd(&g_deg[dst[e]], ew[e]);
        atomicAdd(&g_count[dst[e]], 1);
    }
}
__global__ void k_prep_node() {
    int i = blockIdx.x * blockDim.x + threadIdx.x;
    if (i < NNODES) {
        float d = g_deg[i] + 1.0f;
        g_dinv[i] = rsqrtf(d);
        g_self[i] = 1.0f / d;
    }
}
__global__ void k_scan() {
    int tid = threadIdx.x;
    int c[16];
    int tot = 0;
#pragma unroll
    for (int j = 0; j < 16; j++) { c[j] = tot; tot += g_count[tid * 16 + j]; }
    __shared__ int s[1024];
    s[tid] = tot;
    __syncthreads();
    int mytot = tot;
    for (int off = 1; off < 1024; off <<= 1) {
        int v = (tid >= off) ? s[tid - off] : 0;
        __syncthreads();
        s[tid] += v;
        __syncthreads();
    }
    int incl = s[tid];
    int excl = incl - mytot;
#pragma unroll
    for (int j = 0; j < 16; j++) {
        int v = excl + c[j];
        g_rowptr[tid * 16 + j] = v;
        g_cursor[tid * 16 + j] = v;
    }
    if (tid == 1023) g_rowptr[NNODES] = incl;
}
__global__ void k_fill(const int* __restrict__ src, const int* __restrict__ dst,
                       const float* __restrict__ ew) {
    int e = blockIdx.x * blockDim.x + threadIdx.x;
    if (e < NEDGES) {
        int s = src[e], d = dst[e];
        float norm = g_dinv[s] * ew[e] * g_dinv[d];
        int p = atomicAdd(&g_cursor[d], 1);
        g_csrc[p] = s;
        g_cw[p] = norm;
    }
}

// ---------------- conversions ----------------
__device__ __forceinline__ void split_bf16(float v, bf16& hi, bf16& lo) {
    hi = __float2bfloat16(v);
    lo = __float2bfloat16(v - __bfloat162float(hi));
}

__global__ void k_xconv(const float* __restrict__ x, bf16* __restrict__ hi,
                        bf16* __restrict__ lo, int n) {
    int i = blockIdx.x * blockDim.x + threadIdx.x;
    if (i < n) {
        bf16 h, l;
        split_bf16(x[i], h, l);
        hi[i] = h; lo[i] = l;
    }
}

// W [K,N] f32 -> Wt hi/lo [Npad,K] bf16 (transposed, zero-padded rows)
__global__ void k_wconv(const float* __restrict__ W, bf16* __restrict__ Wh,
                        bf16* __restrict__ Wl, int K, int N) {
    __shared__ float t[32][33];
    int k0 = blockIdx.x * 32, nb0 = blockIdx.y * 32;
    int tx = threadIdx.x, ty = threadIdx.y;
    for (int r = ty; r < 32; r += 8) {
        int nn = nb0 + tx;
        t[r][tx] = (nn < N) ? W[(size_t)(k0 + r) * N + nn] : 0.f;
    }
    __syncthreads();
    for (int r = ty; r < 32; r += 8) {
        int nn = nb0 + r;
        float v = t[tx][r];
        bf16 h, l;
        split_bf16(v, h, l);
        Wh[(size_t)nn * K + k0 + tx] = h;
        Wl[(size_t)nn * K + k0 + tx] = l;
    }
}

// ---------------- aggregation: CSR gather + bias + relu + bf16 split ----------------
__global__ void k_agg(const float* __restrict__ h, const float* __restrict__ bias,
                      bf16* __restrict__ ahi, bf16* __restrict__ alo, int F) {
    int n  = blockIdx.y;
    int f4 = blockIdx.x * blockDim.x + threadIdx.x;
    int F4 = F >> 2;
    if (f4 >= F4) return;
    float4 hv = ((const float4*)(h + (size_t)n * F))[f4];
    float  sc = g_self[n];
    float4 bb = ((const float4*)bias)[f4];
    float4 acc;
    acc.x = sc * hv.x + bb.x;
    acc.y = sc * hv.y + bb.y;
    acc.z = sc * hv.z + bb.z;
    acc.w = sc * hv.w + bb.w;
    int beg = g_rowptr[n], end = g_rowptr[n + 1];
    for (int j = beg; j < end; j++) {
        int   s = g_csrc[j];
        float w = g_cw[j];
        float4 sv = ((const float4*)(h + (size_t)s * F))[f4];
        acc.x += w * sv.x;
        acc.y += w * sv.y;
        acc.z += w * sv.z;
        acc.w += w * sv.w;
    }
    acc.x = fmaxf(acc.x, 0.f); acc.y = fmaxf(acc.y, 0.f);
    acc.z = fmaxf(acc.z, 0.f); acc.w = fmaxf(acc.w, 0.f);
    bf16 h0, l0, h1, l1, h2, l2, h3, l3;
    split_bf16(acc.x, h0, l0); split_bf16(acc.y, h1, l1);
    split_bf16(acc.z, h2, l2); split_bf16(acc.w, h3, l3);
    __nv_bfloat162* ph = ((__nv_bfloat162*)(ahi + (size_t)n * F)) + f4 * 2;
    __nv_bfloat162* pl = ((__nv_bfloat162*)(alo + (size_t)n * F)) + f4 * 2;
    ph[0] = __halves2bfloat162(h0, h1);
    ph[1] = __halves2bfloat162(h2, h3);
    pl[0] = __halves2bfloat162(l0, l1);
    pl[1] = __halves2bfloat162(l2, l3);
}

// ---------------- mma.sync bf16 split GEMM: C = (Ahi+Alo) @ Wt^T ----------------
// CTA 128x128, BK=32, 8 warps (warp tile 32x64), 3-stage cp.async pipeline.
// A [M,K] row-major bf16 (hi+lo), B = Wt [Npad,K] row-major bf16 (hi+lo).
#define BM 128
#define BN 128
#define BKC 32
#define LDT 40                        // padded row stride in bf16 elems (80B)
#define TILE_B (128 * LDT * 2)        // 10240 B per matrix tile
#define STAGE_B (4 * TILE_B)          // Ahi, Alo, Bhi, Blo
#define NSTAGE 3
#define GEMM_SMEM (NSTAGE * STAGE_B)  // 122880 B

template <bool FINAL>
__global__ void __launch_bounds__(256, 1)
k_gemm_mma(const bf16* __restrict__ Ah, const bf16* __restrict__ Al,
           const bf16* __restrict__ Bh, const bf16* __restrict__ Bl,
           float* __restrict__ C, const float* __restrict__ bias,
           int K, int Ncols, int KC) {
    extern __shared__ char smem[];
    uint32_t sb = smem_u32(smem);
    int tid = threadIdx.x;
    int wid = tid >> 5, lane = tid & 31;
    int m0 = blockIdx.y * BM, n0 = blockIdx.x * BN;
    int wm = wid & 3;        // warp m tile (32 rows)
    int wn = wid >> 2;       // warp n half (64 cols)

    const bf16* A0h = Ah + (size_t)m0 * K;
    const bf16* A0l = Al + (size_t)m0 * K;
    const bf16* B0h = Bh + (size_t)n0 * K;
    const bf16* B0l = Bl + (size_t)n0 * K;

    // cp.async load of one BK=32 chunk into stage s
    int lrow = tid >> 2;            // 0..63
    int lg   = tid & 3;             // 16B group within 64B row-chunk
    auto load_chunk = [&](int c, int s) {
        uint32_t tb = sb + s * STAGE_B;
        size_t koff = (size_t)c * BKC;
#pragma unroll
        for (int half = 0; half < 2; half++) {
            int row = lrow + half * 64;
            uint32_t so = (uint32_t)(row * LDT * 2 + lg * 16);
            size_t go = (size_t)row * K + koff + lg * 8;
            cp16(tb + so,              A0h + go);
            cp16(tb + TILE_B + so,     A0l + go);
            cp16(tb + 2 * TILE_B + so, B0h + go);
            cp16(tb + 3 * TILE_B + so, B0l + go);
        }
    };

    // ldmatrix base addresses (stage 0, k=0); quad = lane>>3, r = lane&7
    int quad = lane >> 3, r = lane & 7;
    uint32_t aOff = (uint32_t)(((wm * 32 + (quad & 1) * 8 + r) * LDT + (quad >> 1) * 8) * 2);
    uint32_t bOff = (uint32_t)(((wn * 64 + (quad >> 1) * 8 + r) * LDT + (quad & 1) * 8) * 2);

    float acc[2][8][4];
#pragma unroll
    for (int i = 0; i < 2; i++)
#pragma unroll
        for (int j = 0; j < 8; j++)
#pragma unroll
            for (int q = 0; q < 4; q++) acc[i][j][q] = 0.f;

    load_chunk(0, 0); cp_commit();
    load_chunk(1, 1); cp_commit();

    for (int kc = 0; kc < KC; kc++) {
        int s = kc % NSTAGE;
        if (kc + 1 < KC) cp_wait<1>(); else cp_wait<0>();
        __syncthreads();

        uint32_t stA = sb + s * STAGE_B;
#pragma unroll
        for (int ks = 0; ks < 2; ks++) {
            uint32_t ko = ks * 32;  // 16 elems * 2B
            uint32_t ah[2][4], al[2][4];
#pragma unroll
            for (int mi = 0; mi < 2; mi++) {
                ldsm4(ah[mi], stA + aOff + mi * (16 * LDT * 2) + ko);
                ldsm4(al[mi], stA + TILE_B + aOff + mi * (16 * LDT * 2) + ko);
            }
            uint32_t bh[4][4], bl[4][4];
#pragma unroll
            for (int p = 0; p < 4; p++) {
                ldsm4(bh[p], stA + 2 * TILE_B + bOff + p * (16 * LDT * 2) + ko);
                ldsm4(bl[p], stA + 3 * TILE_B + bOff + p * (16 * LDT * 2) + ko);
            }
#pragma unroll
            for (int mi = 0; mi < 2; mi++)
#pragma unroll
                for (int p = 0; p < 4; p++)
#pragma unroll
                    for (int h = 0; h < 2; h++) {
                        int ni = 2 * p + h;
                        mma16816(acc[mi][ni], ah[mi], &bh[p][h * 2]);
                        mma16816(acc[mi][ni], al[mi], &bh[p][h * 2]);
                        mma16816(acc[mi][ni], ah[mi], &bl[p][h * 2]);
                    }
        }

        if (kc + 2 < KC) {
            load_chunk(kc + 2, (kc + 2) % NSTAGE);
            cp_commit();
        }
        __syncthreads();
    }

    // epilogue: c frag: c0,c1 @ row lane/4, cols (lane%4)*2,+1 ; c2,c3 @ row+8
    int cr = lane >> 2, cc = (lane & 3) * 2;
#pragma unroll
    for (int mi = 0; mi < 2; mi++) {
        int mbase = m0 + wm * 32 + mi * 16;
#pragma unroll
        for (int ni = 0; ni < 8; ni++) {
            int n = n0 + wn * 64 + ni * 8 + cc;
#pragma unroll
            for (int hh = 0; hh < 2; hh++) {
                int m = mbase + cr + hh * 8;
                float v0 = acc[mi][ni][hh * 2 + 0];
                float v1 = acc[mi][ni][hh * 2 + 1];
                if (FINAL) {
                    if (n < Ncols)     C[(size_t)m * Ncols + n]     = v0 + bias[n];
                    if (n + 1 < Ncols) C[(size_t)m * Ncols + n + 1] = v1 + bias[n + 1];
                } else {
                    *(float2*)(C + (size_t)m * Ncols + n) = make_float2(v0, v1);
                }
            }
        }
    }
}

// ---------------- host orchestration ----------------
static inline void launch_gemm(bool final_layer,
                               const bf16* Ah, const bf16* Al,
                               const bf16* Bh, const bf16* Bl,
                               float* C, const float* bias,
                               int K, int N, int Npad) {
    dim3 grid(Npad / BN, NNODES / BM);
    if (final_layer) {
        cudaFuncSetAttribute(k_gemm_mma<true>, cudaFuncAttributeMaxDynamicSharedMemorySize, GEMM_SMEM);
        k_gemm_mma<true><<<grid, 256, GEMM_SMEM>>>(Ah, Al, Bh, Bl, C, bias, K, N, K / BKC);
    } else {
        cudaFuncSetAttribute(k_gemm_mma<false>, cudaFuncAttributeMaxDynamicSharedMemorySize, GEMM_SMEM);
        k_gemm_mma<false><<<grid, 256, GEMM_SMEM>>>(Ah, Al, Bh, Bl, C, bias, K, Npad, K / BKC);
    }
}

static inline void launch_wconv(const float* W, bf16* Wh, bf16* Wl, int K, int N, int Npad) {
    dim3 grid(K / 32, Npad / 32);
    k_wconv<<<grid, dim3(32, 8)>>>(W, Wh, Wl, K, N);
}

static inline void launch_agg(const float* h, const float* bias, bf16* ahi, bf16* alo, int F) {
    int F4 = F >> 2;
    dim3 grid((F4 + 255) / 256, NNODES);
    k_agg<<<grid, 256>>>(h, bias, ahi, alo, F);
}

extern "C" void kernel_launch(void* const* d_in, const int* in_sizes, int n_in,
                              void* d_out, int out_size) {
    const float* x    = (const float*)d_in[0];
    const int*   esrc = (const int*)d_in[1];
    const int*   edst = (const int*)d_in[2];
    const float* ew   = (const float*)d_in[3];
    const float* W1 = (const float*)d_in[4];
    const float* b1 = (const float*)d_in[5];
    const float* W2 = (const float*)d_in[6];
    const float* b2 = (const float*)d_in[7];
    const float* W3 = (const float*)d_in[8];
    const float* b3 = (const float*)d_in[9];
    const float* W4 = (const float*)d_in[10];
    const float* b4 = (const float*)d_in[11];
    const float* Wout = (const float*)d_in[12];
    const float* bout = (const float*)d_in[13];
    float* out = (float*)d_out;

    float* hbuf = nullptr;
    bf16 *ahi = nullptr, *alo = nullptr, *wth = nullptr, *wtl = nullptr;
    cudaGetSymbolAddress((void**)&hbuf, g_h);
    cudaGetSymbolAddress((void**)&ahi, g_ahi);
    cudaGetSymbolAddress((void**)&alo, g_alo);
    cudaGetSymbolAddress((void**)&wth, g_wth);
    cudaGetSymbolAddress((void**)&wtl, g_wtl);

    // graph prep
    k_prep_zero<<<NNODES / 256, 256>>>();
    k_prep_edges<<<NEDGES / 256, 256>>>(esrc, edst, ew);
    k_prep_node<<<NNODES / 256, 256>>>();
    k_scan<<<1, 1024>>>();
    k_fill<<<NEDGES / 256, 256>>>(esrc, edst, ew);

    // layer 1: x[16384,512] @ W1 -> h[.,1024]; agg(+b1,relu,split)
    k_xconv<<<(NNODES * 512 + 255) / 256, 256>>>(x, ahi, alo, NNODES * 512);
    launch_wconv(W1, wth, wtl, 512, 1024, 1024);
    launch_gemm(false, ahi, alo, wth, wtl, hbuf, nullptr, 512, 1024, 1024);
    launch_agg(hbuf, b1, ahi, alo, 1024);

    // layer 2
    launch_wconv(W2, wth, wtl, 1024, 2048, 2048);
    launch_gemm(false, ahi, alo, wth, wtl, hbuf, nullptr, 1024, 2048, 2048);
    launch_agg(hbuf, b2, ahi, alo, 2048);

    // layer 3
    launch_wconv(W3, wth, wtl, 2048, 4096, 4096);
    launch_gemm(false, ahi, alo, wth, wtl, hbuf, nullptr, 2048, 4096, 4096);
    launch_agg(hbuf, b3, ahi, alo, 4096);

    // layer 4
    launch_wconv(W4, wth, wtl, 4096, 2048, 2048);
    launch_gemm(false, ahi, alo, wth, wtl, hbuf, nullptr, 4096, 2048, 2048);
    launch_agg(hbuf, b4, ahi, alo, 2048);

    // output layer: relu(a) @ Wout + bout -> out[16384,1000]
    launch_wconv(Wout, wth, wtl, 2048, 1000, 1024);
    launch_gemm(true, ahi, alo, wth, wtl, out, bout, 2048, 1000, 1024);
}

// round 6
// speedup vs baseline: 2.7998x; 1.1401x over previous
#include <cuda_runtime.h>
#include <cuda_bf16.h>
#include <cstdint>

#define NNODES 16384
#define NEDGES 65536
#define MAXF   4096

typedef __nv_bfloat16 bf16;
typedef __nv_bfloat162 bf162;

// ---------------- scratch (device globals; no allocation) ----------------
__device__ bf16  g_ahi[(size_t)NNODES * MAXF];   // activation buffer A (hi)
__device__ bf16  g_alo[(size_t)NNODES * MAXF];   // activation buffer A (lo)
__device__ bf16  g_ghi[(size_t)NNODES * MAXF];   // buffer B (hi)
__device__ bf16  g_glo[(size_t)NNODES * MAXF];   // buffer B (lo)
__device__ bf16  g_wth[(size_t)4096 * 2048];     // transposed weights hi [Npad,K]
__device__ bf16  g_wtl[(size_t)4096 * 2048];     // transposed weights lo
__device__ float g_deg[NNODES];
__device__ float g_dinv[NNODES];
__device__ float g_self[NNODES];
__device__ int   g_count[NNODES];
__device__ int   g_rowptr[NNODES + 1];
__device__ int   g_cursor[NNODES];
__device__ int   g_csrc[NEDGES];
__device__ float g_cw[NEDGES];

// ---------------- PTX helpers (baseline PTX only) ----------------
__device__ __forceinline__ uint32_t smem_u32(const void* p) {
    uint32_t a;
    asm("{ .reg .u64 t; cvta.to.shared.u64 t, %1; cvt.u32.u64 %0, t; }" : "=r"(a) : "l"(p));
    return a;
}
__device__ __forceinline__ void cp16(uint32_t s, const void* g) {
    asm volatile("cp.async.cg.shared.global [%0], [%1], 16;" :: "r"(s), "l"(g));
}
__device__ __forceinline__ void cp_commit() { asm volatile("cp.async.commit_group;" ::: "memory"); }
template <int N>
__device__ __forceinline__ void cp_wait() { asm volatile("cp.async.wait_group %0;" :: "n"(N) : "memory"); }

__device__ __forceinline__ void ldsm4(uint32_t* r, uint32_t addr) {
    asm volatile("ldmatrix.sync.aligned.m8n8.x4.shared.b16 {%0,%1,%2,%3}, [%4];"
                 : "=r"(r[0]), "=r"(r[1]), "=r"(r[2]), "=r"(r[3]) : "r"(addr));
}
__device__ __forceinline__ void mma16816(float* d, const uint32_t* a, const uint32_t* b) {
    asm volatile(
        "mma.sync.aligned.m16n8k16.row.col.f32.bf16.bf16.f32 "
        "{%0,%1,%2,%3}, {%4,%5,%6,%7}, {%8,%9}, {%0,%1,%2,%3};"
        : "+f"(d[0]), "+f"(d[1]), "+f"(d[2]), "+f"(d[3])
        : "r"(a[0]), "r"(a[1]), "r"(a[2]), "r"(a[3]), "r"(b[0]), "r"(b[1]));
}

__device__ __forceinline__ void split_bf16(float v, bf16& hi, bf16& lo) {
    hi = __float2bfloat16(v);
    lo = __float2bfloat16(v - __bfloat162float(hi));
}

// ---------------- graph prep ----------------
__global__ void k_prep_zero() {
    int i = blockIdx.x * blockDim.x + threadIdx.x;
    if (i < NNODES) { g_deg[i] = 0.f; g_count[i] = 0; }
}
__global__ void k_prep_edges(const int* __restrict__ src, const int* __restrict__ dst,
                             const float* __restrict__ ew) {
    int e = blockIdx.x * blockDim.x + threadIdx.x;
    if (e < NEDGES) {
        atomicAdd(&g_deg[dst[e]], ew[e]);
        atomicAdd(&g_count[dst[e]], 1);
    }
}
__global__ void k_prep_node() {
    int i = blockIdx.x * blockDim.x + threadIdx.x;
    if (i < NNODES) {
        float d = g_deg[i] + 1.0f;
        g_dinv[i] = rsqrtf(d);
        g_self[i] = 1.0f / d;
    }
}
__global__ void k_scan() {
    int tid = threadIdx.x;
    int c[16];
    int tot = 0;
#pragma unroll
    for (int j = 0; j < 16; j++) { c[j] = tot; tot += g_count[tid * 16 + j]; }
    __shared__ int s[1024];
    s[tid] = tot;
    __syncthreads();
    int mytot = tot;
    for (int off = 1; off < 1024; off <<= 1) {
        int v = (tid >= off) ? s[tid - off] : 0;
        __syncthreads();
        s[tid] += v;
        __syncthreads();
    }
    int incl = s[tid];
    int excl = incl - mytot;
#pragma unroll
    for (int j = 0; j < 16; j++) {
        int v = excl + c[j];
        g_rowptr[tid * 16 + j] = v;
        g_cursor[tid * 16 + j] = v;
    }
    if (tid == 1023) g_rowptr[NNODES] = incl;
}
__global__ void k_fill(const int* __restrict__ src, const int* __restrict__ dst,
                       const float* __restrict__ ew) {
    int e = blockIdx.x * blockDim.x + threadIdx.x;
    if (e < NEDGES) {
        int s = src[e], d = dst[e];
        float norm = g_dinv[s] * ew[e] * g_dinv[d];
        int p = atomicAdd(&g_cursor[d], 1);
        g_csrc[p] = s;
        g_cw[p] = norm;
    }
}

// ---------------- weight conversion: W [K,N] f32 -> Wt hi/lo [Npad,K] bf16 ----------------
__global__ void k_wconv(const float* __restrict__ W, bf16* __restrict__ Wh,
                        bf16* __restrict__ Wl, int K, int N) {
    __shared__ float t[32][33];
    int k0 = blockIdx.x * 32, nb0 = blockIdx.y * 32;
    int tx = threadIdx.x, ty = threadIdx.y;
    for (int r = ty; r < 32; r += 8) {
        int nn = nb0 + tx;
        t[r][tx] = (nn < N) ? W[(size_t)(k0 + r) * N + nn] : 0.f;
    }
    __syncthreads();
    for (int r = ty; r < 32; r += 8) {
        int nn = nb0 + r;
        float v = t[tx][r];
        bf16 h, l;
        split_bf16(v, h, l);
        Wh[(size_t)nn * K + k0 + tx] = h;
        Wl[(size_t)nn * K + k0 + tx] = l;
    }
}

// ---------------- aggregation kernels (CSR gather; no bias, no relu unless POST) ---------
// MODE: 0 = f32 input (layer 1, x); 1 = split input (g = agg(a));
//       2 = post (input h split, add bias, relu)  [layer 4]
template <int MODE>
__global__ void k_agg(const float* __restrict__ xf,
                      const bf16* __restrict__ inHi, const bf16* __restrict__ inLo,
                      const float* __restrict__ bias,
                      bf16* __restrict__ outHi, bf16* __restrict__ outLo, int F) {
    int n  = blockIdx.y;
    int f4 = blockIdx.x * blockDim.x + threadIdx.x;
    int F4 = F >> 2;
    if (f4 >= F4) return;

    auto loadrow = [&](int row, float4& v) {
        if (MODE == 0) {
            v = ((const float4*)(xf + (size_t)row * F))[f4];
        } else {
            const bf162* ph = ((const bf162*)(inHi + (size_t)row * F)) + f4 * 2;
            const bf162* pl = ((const bf162*)(inLo + (size_t)row * F)) + f4 * 2;
            float2 h0 = __bfloat1622float2(ph[0]);
            float2 h1 = __bfloat1622float2(ph[1]);
            float2 l0 = __bfloat1622float2(pl[0]);
            float2 l1 = __bfloat1622float2(pl[1]);
            v.x = h0.x + l0.x; v.y = h0.y + l0.y;
            v.z = h1.x + l1.x; v.w = h1.y + l1.y;
        }
    };

    float4 hv; loadrow(n, hv);
    float sc = g_self[n];
    float4 acc = make_float4(sc * hv.x, sc * hv.y, sc * hv.z, sc * hv.w);
    int beg = g_rowptr[n], end = g_rowptr[n + 1];
    for (int j = beg; j < end; j++) {
        int   s = g_csrc[j];
        float w = g_cw[j];
        float4 sv; loadrow(s, sv);
        acc.x += w * sv.x; acc.y += w * sv.y;
        acc.z += w * sv.z; acc.w += w * sv.w;
    }
    if (MODE == 2) {
        float4 bb = ((const float4*)bias)[f4];
        acc.x = fmaxf(acc.x + bb.x, 0.f);
        acc.y = fmaxf(acc.y + bb.y, 0.f);
        acc.z = fmaxf(acc.z + bb.z, 0.f);
        acc.w = fmaxf(acc.w + bb.w, 0.f);
    }
    bf16 h0, l0, h1, l1, h2, l2, h3, l3;
    split_bf16(acc.x, h0, l0); split_bf16(acc.y, h1, l1);
    split_bf16(acc.z, h2, l2); split_bf16(acc.w, h3, l3);
    bf162* ph = ((bf162*)(outHi + (size_t)n * F)) + f4 * 2;
    bf162* pl = ((bf162*)(outLo + (size_t)n * F)) + f4 * 2;
    ph[0] = __halves2bfloat162(h0, h1);
    ph[1] = __halves2bfloat162(h2, h3);
    pl[0] = __halves2bfloat162(l0, l1);
    pl[1] = __halves2bfloat162(l2, l3);
}

// ---------------- mma.sync bf16 split GEMM ----------------
// CTA 128x256, 512 threads (16 warps, warp tile 32x64), BK=32, 3-stage cp.async.
// A [M,K] split bf16, B = Wt [Npad,K] split bf16.
// MODE 0: out split, +bias, relu   (agg-first conv layers)
// MODE 1: out split, no bias/relu  (layer 4, agg after)
// MODE 2: out f32, +bias, N guard  (final layer)
#define BM 128
#define BN 256
#define BKC 32
#define LDT 40                          // bf16 elems per row (80 B)
#define A_T (128 * LDT * 2)             // 10240 B
#define B_T (256 * LDT * 2)             // 20480 B
#define STAGE_B (2 * A_T + 2 * B_T)     // 61440 B: Ah, Al, Bh, Bl
#define NSTAGE 3
#define GEMM_SMEM (NSTAGE * STAGE_B)    // 184320 B

template <int MODE>
__global__ void __launch_bounds__(512, 1)
k_gemm_mma(const bf16* __restrict__ Ah, const bf16* __restrict__ Al,
           const bf16* __restrict__ Bh, const bf16* __restrict__ Bl,
           bf16* __restrict__ OHi, bf16* __restrict__ OLo,
           float* __restrict__ Cf, const float* __restrict__ bias,
           int K, int Ncols, int KC) {
    extern __shared__ char smem[];
    uint32_t sb = smem_u32(smem);
    int tid = threadIdx.x;
    int wid = tid >> 5, lane = tid & 31;
    int m0 = blockIdx.y * BM, n0 = blockIdx.x * BN;
    int wm = wid & 3;        // warp m tile (32 rows)
    int wn = wid >> 2;       // warp n tile (64 cols, 0..3)

    const bf16* A0h = Ah + (size_t)m0 * K;
    const bf16* A0l = Al + (size_t)m0 * K;
    const bf16* B0h = Bh + (size_t)n0 * K;
    const bf16* B0l = Bl + (size_t)n0 * K;

    int lrow = tid >> 2;       // 0..127
    int lg   = tid & 3;        // 16B group
    auto load_chunk = [&](int c, int s) {
        uint32_t tb = sb + s * STAGE_B;
        size_t koff = (size_t)c * BKC;
        uint32_t so = (uint32_t)(lrow * (LDT * 2) + lg * 16);
        size_t go = (size_t)lrow * K + koff + lg * 8;
        cp16(tb + so,       A0h + go);
        cp16(tb + A_T + so, A0l + go);
#pragma unroll
        for (int half = 0; half < 2; half++) {
            int row = lrow + half * 128;
            uint32_t sob = (uint32_t)(row * (LDT * 2) + lg * 16);
            size_t gob = (size_t)row * K + koff + lg * 8;
            cp16(tb + 2 * A_T + sob,       B0h + gob);
            cp16(tb + 2 * A_T + B_T + sob, B0l + gob);
        }
    };

    int quad = lane >> 3, r = lane & 7;
    uint32_t aOff = (uint32_t)(((wm * 32 + (quad & 1) * 8 + r) * LDT + (quad >> 1) * 8) * 2);
    uint32_t bOff = (uint32_t)(((wn * 64 + (quad >> 1) * 8 + r) * LDT + (quad & 1) * 8) * 2);

    float acc[2][8][4];
#pragma unroll
    for (int i = 0; i < 2; i++)
#pragma unroll
        for (int j = 0; j < 8; j++)
#pragma unroll
            for (int q = 0; q < 4; q++) acc[i][j][q] = 0.f;

    load_chunk(0, 0); cp_commit();
    load_chunk(1, 1); cp_commit();

    for (int kc = 0; kc < KC; kc++) {
        int s = kc % NSTAGE;
        if (kc + 1 < KC) cp_wait<1>(); else cp_wait<0>();
        __syncthreads();

        uint32_t st = sb + s * STAGE_B;
#pragma unroll
        for (int ks = 0; ks < 2; ks++) {
            uint32_t ko = ks * 32;  // 16 elems * 2B
            uint32_t ah[2][4], al[2][4];
#pragma unroll
            for (int mi = 0; mi < 2; mi++) {
                ldsm4(ah[mi], st + aOff + mi * (16 * LDT * 2) + ko);
                ldsm4(al[mi], st + A_T + aOff + mi * (16 * LDT * 2) + ko);
            }
#pragma unroll
            for (int p = 0; p < 4; p++) {
                uint32_t bh[4], bl[4];
                ldsm4(bh, st + 2 * A_T + bOff + p * (16 * LDT * 2) + ko);
                ldsm4(bl, st + 2 * A_T + B_T + bOff + p * (16 * LDT * 2) + ko);
#pragma unroll
                for (int mi = 0; mi < 2; mi++)
#pragma unroll
                    for (int h = 0; h < 2; h++) {
                        int ni = 2 * p + h;
                        mma16816(acc[mi][ni], ah[mi], &bh[h * 2]);
                        mma16816(acc[mi][ni], al[mi], &bh[h * 2]);
                        mma16816(acc[mi][ni], ah[mi], &bl[h * 2]);
                    }
            }
        }

        if (kc + 2 < KC) {
            load_chunk(kc + 2, (kc + 2) % NSTAGE);
            cp_commit();
        }
        __syncthreads();
    }

    // epilogue
    int cr = lane >> 2, cc = (lane & 3) * 2;
#pragma unroll
    for (int mi = 0; mi < 2; mi++) {
#pragma unroll
        for (int ni = 0; ni < 8; ni++) {
            int n = n0 + wn * 64 + ni * 8 + cc;
#pragma unroll
            for (int hh = 0; hh < 2; hh++) {
                int m = m0 + wm * 32 + mi * 16 + cr + hh * 8;
                float v0 = acc[mi][ni][hh * 2 + 0];
                float v1 = acc[mi][ni][hh * 2 + 1];
                if (MODE == 2) {
                    if (n < Ncols)     Cf[(size_t)m * Ncols + n]     = v0 + bias[n];
                    if (n + 1 < Ncols) Cf[(size_t)m * Ncols + n + 1] = v1 + bias[n + 1];
                } else {
                    if (MODE == 0) {
                        v0 = fmaxf(v0 + bias[n], 0.f);
                        v1 = fmaxf(v1 + bias[n + 1], 0.f);
                    }
                    bf16 h0, l0, h1, l1;
                    split_bf16(v0, h0, l0);
                    split_bf16(v1, h1, l1);
                    *(bf162*)(OHi + (size_t)m * Ncols + n) = __halves2bfloat162(h0, h1);
                    *(bf162*)(OLo + (size_t)m * Ncols + n) = __halves2bfloat162(l0, l1);
                }
            }
        }
    }
}

// ---------------- host orchestration ----------------
static inline void launch_gemm(int mode,
                               const bf16* Ah, const bf16* Al,
                               const bf16* Bh, const bf16* Bl,
                               bf16* OHi, bf16* OLo, float* Cf, const float* bias,
                               int K, int Ncols, int Npad) {
    dim3 grid(Npad / BN, NNODES / BM);
    if (mode == 0) {
        cudaFuncSetAttribute(k_gemm_mma<0>, cudaFuncAttributeMaxDynamicSharedMemorySize, GEMM_SMEM);
        k_gemm_mma<0><<<grid, 512, GEMM_SMEM>>>(Ah, Al, Bh, Bl, OHi, OLo, Cf, bias, K, Ncols, K / BKC);
    } else if (mode == 1) {
        cudaFuncSetAttribute(k_gemm_mma<1>, cudaFuncAttributeMaxDynamicSharedMemorySize, GEMM_SMEM);
        k_gemm_mma<1><<<grid, 512, GEMM_SMEM>>>(Ah, Al, Bh, Bl, OHi, OLo, Cf, bias, K, Ncols, K / BKC);
    } else {
        cudaFuncSetAttribute(k_gemm_mma<2>, cudaFuncAttributeMaxDynamicSharedMemorySize, GEMM_SMEM);
        k_gemm_mma<2><<<grid, 512, GEMM_SMEM>>>(Ah, Al, Bh, Bl, OHi, OLo, Cf, bias, K, Ncols, K / BKC);
    }
}

static inline void launch_wconv(const float* W, bf16* Wh, bf16* Wl, int K, int N, int Npad) {
    dim3 grid(K / 32, Npad / 32);
    k_wconv<<<grid, dim3(32, 8)>>>(W, Wh, Wl, K, N);
}

extern "C" void kernel_launch(void* const* d_in, const int* in_sizes, int n_in,
                              void* d_out, int out_size) {
    const float* x    = (const float*)d_in[0];
    const int*   esrc = (const int*)d_in[1];
    const int*   edst = (const int*)d_in[2];
    const float* ew   = (const float*)d_in[3];
    const float* W1 = (const float*)d_in[4];
    const float* b1 = (const float*)d_in[5];
    const float* W2 = (const float*)d_in[6];
    const float* b2 = (const float*)d_in[7];
    const float* W3 = (const float*)d_in[8];
    const float* b3 = (const float*)d_in[9];
    const float* W4 = (const float*)d_in[10];
    const float* b4 = (const float*)d_in[11];
    const float* Wout = (const float*)d_in[12];
    const float* bout = (const float*)d_in[13];
    float* out = (float*)d_out;

    bf16 *ahi, *alo, *ghi, *glo, *wth, *wtl;
    cudaGetSymbolAddress((void**)&ahi, g_ahi);
    cudaGetSymbolAddress((void**)&alo, g_alo);
    cudaGetSymbolAddress((void**)&ghi, g_ghi);
    cudaGetSymbolAddress((void**)&glo, g_glo);
    cudaGetSymbolAddress((void**)&wth, g_wth);
    cudaGetSymbolAddress((void**)&wtl, g_wtl);

    // graph prep
    k_prep_zero<<<NNODES / 256, 256>>>();
    k_prep_edges<<<NEDGES / 256, 256>>>(esrc, edst, ew);
    k_prep_node<<<NNODES / 256, 256>>>();
    k_scan<<<1, 1024>>>();
    k_fill<<<NEDGES / 256, 256>>>(esrc, edst, ew);

    auto agg_grid = [](int F) { return dim3(((F >> 2) + 255) / 256, NNODES); };

    // L1: g = agg(x) [512]; a = relu(g W1 + b1) [1024]
    k_agg<0><<<agg_grid(512), 256>>>(x, nullptr, nullptr, nullptr, ghi, glo, 512);
    launch_wconv(W1, wth, wtl, 512, 1024, 1024);
    launch_gemm(0, ghi, glo, wth, wtl, ahi, alo, nullptr, b1, 512, 1024, 1024);

    // L2: g = agg(a) [1024]; a = relu(g W2 + b2) [2048]
    k_agg<1><<<agg_grid(1024), 256>>>(nullptr, ahi, alo, nullptr, ghi, glo, 1024);
    launch_wconv(W2, wth, wtl, 1024, 2048, 2048);
    launch_gemm(0, ghi, glo, wth, wtl, ahi, alo, nullptr, b2, 1024, 2048, 2048);

    // L3: g = agg(a) [2048]; a = relu(g W3 + b3) [4096]
    k_agg<1><<<agg_grid(2048), 256>>>(nullptr, ahi, alo, nullptr, ghi, glo, 2048);
    launch_wconv(W3, wth, wtl, 2048, 4096, 4096);
    launch_gemm(0, ghi, glo, wth, wtl, ahi, alo, nullptr, b3, 2048, 4096, 4096);

    // L4 (agg after): h = a W4 [2048]; a = relu(agg(h) + b4)
    launch_wconv(W4, wth, wtl, 4096, 2048, 2048);
    launch_gemm(1, ahi, alo, wth, wtl, ghi, glo, nullptr, nullptr, 4096, 2048, 2048);
    k_agg<2><<<agg_grid(2048), 256>>>(nullptr, ghi, glo, b4, ahi, alo, 2048);

    // L5 (output): out = a Wout + bout [1000]
    launch_wconv(Wout, wth, wtl, 2048, 1000, 1024);
    launch_gemm(2, ahi, alo, wth, wtl, nullptr, nullptr, out, bout, 2048, 1000, 1024);
}

// round 7
// speedup vs baseline: 4.0063x; 1.4309x over previous
#include <cuda_runtime.h>
#include <cuda_fp16.h>
#include <cstdint>

#define NNODES 16384
#define NEDGES 65536
#define MAXF   4096

// ---------------- scratch (device globals; no allocation) ----------------
__device__ __half g_ahi[(size_t)NNODES * MAXF];   // activation buffer A (hi)
__device__ __half g_alo[(size_t)NNODES * MAXF];   // activation buffer A (lo)
__device__ __half g_ghi[(size_t)NNODES * MAXF];   // buffer B (hi)
__device__ __half g_glo[(size_t)NNODES * MAXF];   // buffer B (lo)
__device__ __half g_wt[(size_t)4096 * 4096];      // transposed weights fp16 [Npad,K]
__device__ float g_deg[NNODES];
__device__ float g_dinv[NNODES];
__device__ float g_self[NNODES];
__device__ int   g_count[NNODES];
__device__ int   g_rowptr[NNODES + 1];
__device__ int   g_cursor[NNODES];
__device__ int   g_csrc[NEDGES];
__device__ float g_cw[NEDGES];

// ---------------- PTX helpers (baseline PTX only) ----------------
__device__ __forceinline__ uint32_t smem_u32(const void* p) {
    uint32_t a;
    asm("{ .reg .u64 t; cvta.to.shared.u64 t, %1; cvt.u32.u64 %0, t; }" : "=r"(a) : "l"(p));
    return a;
}
__device__ __forceinline__ void cp16(uint32_t s, const void* g) {
    asm volatile("cp.async.cg.shared.global [%0], [%1], 16;" :: "r"(s), "l"(g));
}
__device__ __forceinline__ void cp_commit() { asm volatile("cp.async.commit_group;" ::: "memory"); }
template <int N>
__device__ __forceinline__ void cp_wait() { asm volatile("cp.async.wait_group %0;" :: "n"(N) : "memory"); }

__device__ __forceinline__ void ldsm4(uint32_t* r, uint32_t addr) {
    asm volatile("ldmatrix.sync.aligned.m8n8.x4.shared.b16 {%0,%1,%2,%3}, [%4];"
                 : "=r"(r[0]), "=r"(r[1]), "=r"(r[2]), "=r"(r[3]) : "r"(addr));
}
__device__ __forceinline__ void mma16816(float* d, const uint32_t* a, const uint32_t* b) {
    asm volatile(
        "mma.sync.aligned.m16n8k16.row.col.f32.f16.f16.f32 "
        "{%0,%1,%2,%3}, {%4,%5,%6,%7}, {%8,%9}, {%0,%1,%2,%3};"
        : "+f"(d[0]), "+f"(d[1]), "+f"(d[2]), "+f"(d[3])
        : "r"(a[0]), "r"(a[1]), "r"(a[2]), "r"(a[3]), "r"(b[0]), "r"(b[1]));
}

__device__ __forceinline__ void split_f16(float v, __half& hi, __half& lo) {
    hi = __float2half(v);
    lo = __float2half(v - __half2float(hi));
}

// ---------------- graph prep ----------------
__global__ void k_prep_zero() {
    int i = blockIdx.x * blockDim.x + threadIdx.x;
    if (i < NNODES) { g_deg[i] = 0.f; g_count[i] = 0; }
}
__global__ void k_prep_edges(const int* __restrict__ src, const int* __restrict__ dst,
                             const float* __restrict__ ew) {
    int e = blockIdx.x * blockDim.x + threadIdx.x;
    if (e < NEDGES) {
        atomicAdd(&g_deg[dst[e]], ew[e]);
        atomicAdd(&g_count[dst[e]], 1);
    }
}
__global__ void k_prep_node() {
    int i = blockIdx.x * blockDim.x + threadIdx.x;
    if (i < NNODES) {
        float d = g_deg[i] + 1.0f;
        g_dinv[i] = rsqrtf(d);
        g_self[i] = 1.0f / d;
    }
}
__global__ void k_scan() {
    int tid = threadIdx.x;
    int c[16];
    int tot = 0;
#pragma unroll
    for (int j = 0; j < 16; j++) { c[j] = tot; tot += g_count[tid * 16 + j]; }
    __shared__ int s[1024];
    s[tid] = tot;
    __syncthreads();
    int mytot = tot;
    for (int off = 1; off < 1024; off <<= 1) {
        int v = (tid >= off) ? s[tid - off] : 0;
        __syncthreads();
        s[tid] += v;
        __syncthreads();
    }
    int incl = s[tid];
    int excl = incl - mytot;
#pragma unroll
    for (int j = 0; j < 16; j++) {
        int v = excl + c[j];
        g_rowptr[tid * 16 + j] = v;
        g_cursor[tid * 16 + j] = v;
    }
    if (tid == 1023) g_rowptr[NNODES] = incl;
}
__global__ void k_fill(const int* __restrict__ src, const int* __restrict__ dst,
                       const float* __restrict__ ew) {
    int e = blockIdx.x * blockDim.x + threadIdx.x;
    if (e < NEDGES) {
        int s = src[e], d = dst[e];
        float norm = g_dinv[s] * ew[e] * g_dinv[d];
        int p = atomicAdd(&g_cursor[d], 1);
        g_csrc[p] = s;
        g_cw[p] = norm;
    }
}

// ---------------- weight conversion: W [K,N] f32 -> Wt fp16 [Npad,K] ----------------
__global__ void k_wconv(const float* __restrict__ W, __half* __restrict__ Wt,
                        int K, int N) {
    __shared__ float t[32][33];
    int k0 = blockIdx.x * 32, nb0 = blockIdx.y * 32;
    int tx = threadIdx.x, ty = threadIdx.y;
    for (int r = ty; r < 32; r += 8) {
        int nn = nb0 + tx;
        t[r][tx] = (nn < N) ? W[(size_t)(k0 + r) * N + nn] : 0.f;
    }
    __syncthreads();
    for (int r = ty; r < 32; r += 8) {
        int nn = nb0 + r;
        Wt[(size_t)nn * K + k0 + tx] = __float2half(t[tx][r]);
    }
}

// ---------------- aggregation kernels (CSR gather) ----------------
// MODE: 0 = f32 input (layer 1, x); 1 = split fp16 input;
//       2 = post (input split, add bias, relu) [layer 4]
template <int MODE>
__global__ void k_agg(const float* __restrict__ xf,
                      const __half* __restrict__ inHi, const __half* __restrict__ inLo,
                      const float* __restrict__ bias,
                      __half* __restrict__ outHi, __half* __restrict__ outLo, int F) {
    int n  = blockIdx.y;
    int f4 = blockIdx.x * blockDim.x + threadIdx.x;
    int F4 = F >> 2;
    if (f4 >= F4) return;

    auto loadrow = [&](int row, float4& v) {
        if (MODE == 0) {
            v = ((const float4*)(xf + (size_t)row * F))[f4];
        } else {
            const __half2* ph = ((const __half2*)(inHi + (size_t)row * F)) + f4 * 2;
            const __half2* pl = ((const __half2*)(inLo + (size_t)row * F)) + f4 * 2;
            float2 h0 = __half22float2(ph[0]);
            float2 h1 = __half22float2(ph[1]);
            float2 l0 = __half22float2(pl[0]);
            float2 l1 = __half22float2(pl[1]);
            v.x = h0.x + l0.x; v.y = h0.y + l0.y;
            v.z = h1.x + l1.x; v.w = h1.y + l1.y;
        }
    };

    float4 hv; loadrow(n, hv);
    float sc = g_self[n];
    float4 acc = make_float4(sc * hv.x, sc * hv.y, sc * hv.z, sc * hv.w);
    int beg = g_rowptr[n], end = g_rowptr[n + 1];
    for (int j = beg; j < end; j++) {
        int   s = g_csrc[j];
        float w = g_cw[j];
        float4 sv; loadrow(s, sv);
        acc.x += w * sv.x; acc.y += w * sv.y;
        acc.z += w * sv.z; acc.w += w * sv.w;
    }
    if (MODE == 2) {
        float4 bb = ((const float4*)bias)[f4];
        acc.x = fmaxf(acc.x + bb.x, 0.f);
        acc.y = fmaxf(acc.y + bb.y, 0.f);
        acc.z = fmaxf(acc.z + bb.z, 0.f);
        acc.w = fmaxf(acc.w + bb.w, 0.f);
    }
    __half h0, l0, h1, l1, h2, l2, h3, l3;
    split_f16(acc.x, h0, l0); split_f16(acc.y, h1, l1);
    split_f16(acc.z, h2, l2); split_f16(acc.w, h3, l3);
    __half2* ph = ((__half2*)(outHi + (size_t)n * F)) + f4 * 2;
    __half2* pl = ((__half2*)(outLo + (size_t)n * F)) + f4 * 2;
    ph[0] = __halves2half2(h0, h1);
    ph[1] = __halves2half2(h2, h3);
    pl[0] = __halves2half2(l0, l1);
    pl[1] = __halves2half2(l2, l3);
}

// ---------------- mma.sync fp16 split-A GEMM ----------------
// CTA 128x256, 512 threads (16 warps, warp tile 32x64), BK=32, 3-stage cp.async.
// A [M,K] split fp16 (hi+lo), B = Wt [Npad,K] single fp16.
// C = (Ah + Al) @ B^T : 2 MMA terms.
// MODE 0: out split, +bias, relu   (agg-first conv layers)
// MODE 1: out split, no bias/relu  (layer 4, agg after)
// MODE 2: out f32, +bias, N guard  (final layer)
#define BM 128
#define BN 256
#define BKC 32
#define LDT 40                          // fp16 elems per row (80 B)
#define A_T (128 * LDT * 2)             // 10240 B
#define B_T (256 * LDT * 2)             // 20480 B
#define STAGE_B (2 * A_T + B_T)         // 40960 B: Ah, Al, B
#define NSTAGE 3
#define GEMM_SMEM (NSTAGE * STAGE_B)    // 122880 B

template <int MODE>
__global__ void __launch_bounds__(512, 1)
k_gemm_mma(const __half* __restrict__ Ah, const __half* __restrict__ Al,
           const __half* __restrict__ Bw,
           __half* __restrict__ OHi, __half* __restrict__ OLo,
           float* __restrict__ Cf, const float* __restrict__ bias,
           int K, int Ncols, int KC) {
    extern __shared__ char smem[];
    uint32_t sb = smem_u32(smem);
    int tid = threadIdx.x;
    int wid = tid >> 5, lane = tid & 31;
    int m0 = blockIdx.y * BM, n0 = blockIdx.x * BN;
    int wm = wid & 3;        // warp m tile (32 rows)
    int wn = wid >> 2;       // warp n tile (64 cols, 0..3)

    const __half* A0h = Ah + (size_t)m0 * K;
    const __half* A0l = Al + (size_t)m0 * K;
    const __half* B0  = Bw + (size_t)n0 * K;

    int lrow = tid >> 2;       // 0..127
    int lg   = tid & 3;        // 16B group
    auto load_chunk = [&](int c, int s) {
        uint32_t tb = sb + s * STAGE_B;
        size_t koff = (size_t)c * BKC;
        uint32_t so = (uint32_t)(lrow * (LDT * 2) + lg * 16);
        size_t go = (size_t)lrow * K + koff + lg * 8;
        cp16(tb + so,       A0h + go);
        cp16(tb + A_T + so, A0l + go);
#pragma unroll
        for (int half = 0; half < 2; half++) {
            int row = lrow + half * 128;
            uint32_t sob = (uint32_t)(row * (LDT * 2) + lg * 16);
            size_t gob = (size_t)row * K + koff + lg * 8;
            cp16(tb + 2 * A_T + sob, B0 + gob);
        }
    };

    int quad = lane >> 3, r = lane & 7;
    uint32_t aOff = (uint32_t)(((wm * 32 + (quad & 1) * 8 + r) * LDT + (quad >> 1) * 8) * 2);
    uint32_t bOff = (uint32_t)(((wn * 64 + (quad >> 1) * 8 + r) * LDT + (quad & 1) * 8) * 2);

    float acc[2][8][4];
#pragma unroll
    for (int i = 0; i < 2; i++)
#pragma unroll
        for (int j = 0; j < 8; j++)
#pragma unroll
            for (int q = 0; q < 4; q++) acc[i][j][q] = 0.f;

    load_chunk(0, 0); cp_commit();
    load_chunk(1, 1); cp_commit();

    for (int kc = 0; kc < KC; kc++) {
        int s = kc % NSTAGE;
        if (kc + 1 < KC) cp_wait<1>(); else cp_wait<0>();
        __syncthreads();

        uint32_t st = sb + s * STAGE_B;
#pragma unroll
        for (int ks = 0; ks < 2; ks++) {
            uint32_t ko = ks * 32;  // 16 elems * 2B
            uint32_t ah[2][4], al[2][4];
#pragma unroll
            for (int mi = 0; mi < 2; mi++) {
                ldsm4(ah[mi], st + aOff + mi * (16 * LDT * 2) + ko);
                ldsm4(al[mi], st + A_T + aOff + mi * (16 * LDT * 2) + ko);
            }
#pragma unroll
            for (int p = 0; p < 4; p++) {
                uint32_t bf[4];
                ldsm4(bf, st + 2 * A_T + bOff + p * (16 * LDT * 2) + ko);
#pragma unroll
                for (int mi = 0; mi < 2; mi++)
#pragma unroll
                    for (int h = 0; h < 2; h++) {
                        int ni = 2 * p + h;
                        mma16816(acc[mi][ni], ah[mi], &bf[h * 2]);
                        mma16816(acc[mi][ni], al[mi], &bf[h * 2]);
                    }
            }
        }

        if (kc + 2 < KC) {
            load_chunk(kc + 2, (kc + 2) % NSTAGE);
            cp_commit();
        }
        __syncthreads();
    }

    // epilogue
    int cr = lane >> 2, cc = (lane & 3) * 2;
#pragma unroll
    for (int mi = 0; mi < 2; mi++) {
#pragma unroll
        for (int ni = 0; ni < 8; ni++) {
            int n = n0 + wn * 64 + ni * 8 + cc;
#pragma unroll
            for (int hh = 0; hh < 2; hh++) {
                int m = m0 + wm * 32 + mi * 16 + cr + hh * 8;
                float v0 = acc[mi][ni][hh * 2 + 0];
                float v1 = acc[mi][ni][hh * 2 + 1];
                if (MODE == 2) {
                    if (n < Ncols)     Cf[(size_t)m * Ncols + n]     = v0 + bias[n];
                    if (n + 1 < Ncols) Cf[(size_t)m * Ncols + n + 1] = v1 + bias[n + 1];
                } else {
                    if (MODE == 0) {
                        v0 = fmaxf(v0 + bias[n], 0.f);
                        v1 = fmaxf(v1 + bias[n + 1], 0.f);
                    }
                    __half h0, l0, h1, l1;
                    split_f16(v0, h0, l0);
                    split_f16(v1, h1, l1);
                    *(__half2*)(OHi + (size_t)m * Ncols + n) = __halves2half2(h0, h1);
                    *(__half2*)(OLo + (size_t)m * Ncols + n) = __halves2half2(l0, l1);
                }
            }
        }
    }
}

// ---------------- host orchestration ----------------
static inline void launch_gemm(int mode,
                               const __half* Ah, const __half* Al, const __half* Bw,
                               __half* OHi, __half* OLo, float* Cf, const float* bias,
                               int K, int Ncols, int Npad) {
    dim3 grid(Npad / BN, NNODES / BM);
    if (mode == 0) {
        cudaFuncSetAttribute(k_gemm_mma<0>, cudaFuncAttributeMaxDynamicSharedMemorySize, GEMM_SMEM);
        k_gemm_mma<0><<<grid, 512, GEMM_SMEM>>>(Ah, Al, Bw, OHi, OLo, Cf, bias, K, Ncols, K / BKC);
    } else if (mode == 1) {
        cudaFuncSetAttribute(k_gemm_mma<1>, cudaFuncAttributeMaxDynamicSharedMemorySize, GEMM_SMEM);
        k_gemm_mma<1><<<grid, 512, GEMM_SMEM>>>(Ah, Al, Bw, OHi, OLo, Cf, bias, K, Ncols, K / BKC);
    } else {
        cudaFuncSetAttribute(k_gemm_mma<2>, cudaFuncAttributeMaxDynamicSharedMemorySize, GEMM_SMEM);
        k_gemm_mma<2><<<grid, 512, GEMM_SMEM>>>(Ah, Al, Bw, OHi, OLo, Cf, bias, K, Ncols, K / BKC);
    }
}

static inline void launch_wconv(const float* W, __half* Wt, int K, int N, int Npad) {
    dim3 grid(K / 32, Npad / 32);
    k_wconv<<<grid, dim3(32, 8)>>>(W, Wt, K, N);
}

extern "C" void kernel_launch(void* const* d_in, const int* in_sizes, int n_in,
                              void* d_out, int out_size) {
    const float* x    = (const float*)d_in[0];
    const int*   esrc = (const int*)d_in[1];
    const int*   edst = (const int*)d_in[2];
    const float* ew   = (const float*)d_in[3];
    const float* W1 = (const float*)d_in[4];
    const float* b1 = (const float*)d_in[5];
    const float* W2 = (const float*)d_in[6];
    const float* b2 = (const float*)d_in[7];
    const float* W3 = (const float*)d_in[8];
    const float* b3 = (const float*)d_in[9];
    const float* W4 = (const float*)d_in[10];
    const float* b4 = (const float*)d_in[11];
    const float* Wout = (const float*)d_in[12];
    const float* bout = (const float*)d_in[13];
    float* out = (float*)d_out;

    __half *ahi, *alo, *ghi, *glo, *wt;
    cudaGetSymbolAddress((void**)&ahi, g_ahi);
    cudaGetSymbolAddress((void**)&alo, g_alo);
    cudaGetSymbolAddress((void**)&ghi, g_ghi);
    cudaGetSymbolAddress((void**)&glo, g_glo);
    cudaGetSymbolAddress((void**)&wt, g_wt);

    // graph prep
    k_prep_zero<<<NNODES / 256, 256>>>();
    k_prep_edges<<<NEDGES / 256, 256>>>(esrc, edst, ew);
    k_prep_node<<<NNODES / 256, 256>>>();
    k_scan<<<1, 1024>>>();
    k_fill<<<NEDGES / 256, 256>>>(esrc, edst, ew);

    auto agg_grid = [](int F) { return dim3(((F >> 2) + 255) / 256, NNODES); };

    // L1: g = agg(x) [512]; a = relu(g W1 + b1) [1024]
    k_agg<0><<<agg_grid(512), 256>>>(x, nullptr, nullptr, nullptr, ghi, glo, 512);
    launch_wconv(W1, wt, 512, 1024, 1024);
    launch_gemm(0, ghi, glo, wt, ahi, alo, nullptr, b1, 512, 1024, 1024);

    // L2: g = agg(a) [1024]; a = relu(g W2 + b2) [2048]
    k_agg<1><<<agg_grid(1024), 256>>>(nullptr, ahi, alo, nullptr, ghi, glo, 1024);
    launch_wconv(W2, wt, 1024, 2048, 2048);
    launch_gemm(0, ghi, glo, wt, ahi, alo, nullptr, b2, 1024, 2048, 2048);

    // L3: g = agg(a) [2048]; a = relu(g W3 + b3) [4096]
    k_agg<1><<<agg_grid(2048), 256>>>(nullptr, ahi, alo, nullptr, ghi, glo, 2048);
    launch_wconv(W3, wt, 2048, 4096, 4096);
    launch_gemm(0, ghi, glo, wt, ahi, alo, nullptr, b3, 2048, 4096, 4096);

    // L4 (agg after): h = a W4 [2048]; a = relu(agg(h) + b4)
    launch_wconv(W4, wt, 4096, 2048, 2048);
    launch_gemm(1, ahi, alo, wt, ghi, glo, nullptr, nullptr, 4096, 2048, 2048);
    k_agg<2><<<agg_grid(2048), 256>>>(nullptr, ghi, glo, b4, ahi, alo, 2048);

    // L5 (output): out = a Wout + bout [1000]
    launch_wconv(Wout, wt, 2048, 1000, 1024);
    launch_gemm(2, ahi, alo, wt, nullptr, nullptr, out, bout, 2048, 1000, 1024);
}

// round 8
// speedup vs baseline: 4.0119x; 1.0014x over previous
#include <cuda_runtime.h>
#include <cuda_fp16.h>
#include <cstdint>

#define NNODES 16384
#define NEDGES 65536
#define MAXF   4096

// ---------------- scratch (device globals; no allocation) ----------------
__device__ __half g_ahi[(size_t)NNODES * MAXF];   // activation buffer A (hi)
__device__ __half g_alo[(size_t)NNODES * MAXF];   // activation buffer A (lo)
__device__ __half g_ghi[(size_t)NNODES * MAXF];   // buffer B (hi)
__device__ __half g_glo[(size_t)NNODES * MAXF];   // buffer B (lo)
__device__ __half g_wt[(size_t)4096 * 4096];      // transposed weights fp16 [Npad,K]
__device__ float g_deg[NNODES];
__device__ float g_dinv[NNODES];
__device__ float g_self[NNODES];
__device__ int   g_count[NNODES];
__device__ int   g_rowptr[NNODES + 1];
__device__ int   g_cursor[NNODES];
__device__ int   g_csrc[NEDGES];
__device__ float g_cw[NEDGES];

// ---------------- PTX helpers (baseline PTX only) ----------------
__device__ __forceinline__ uint32_t smem_u32(const void* p) {
    uint32_t a;
    asm("{ .reg .u64 t; cvta.to.shared.u64 t, %1; cvt.u32.u64 %0, t; }" : "=r"(a) : "l"(p));
    return a;
}
__device__ __forceinline__ void cp16(uint32_t s, const void* g) {
    asm volatile("cp.async.cg.shared.global [%0], [%1], 16;" :: "r"(s), "l"(g));
}
__device__ __forceinline__ void cp_commit() { asm volatile("cp.async.commit_group;" ::: "memory"); }
template <int N>
__device__ __forceinline__ void cp_wait() { asm volatile("cp.async.wait_group %0;" :: "n"(N) : "memory"); }

__device__ __forceinline__ void ldsm4(uint32_t* r, uint32_t addr) {
    asm volatile("ldmatrix.sync.aligned.m8n8.x4.shared.b16 {%0,%1,%2,%3}, [%4];"
                 : "=r"(r[0]), "=r"(r[1]), "=r"(r[2]), "=r"(r[3]) : "r"(addr));
}
__device__ __forceinline__ void mma16816(float* d, const uint32_t* a, const uint32_t* b) {
    asm volatile(
        "mma.sync.aligned.m16n8k16.row.col.f32.f16.f16.f32 "
        "{%0,%1,%2,%3}, {%4,%5,%6,%7}, {%8,%9}, {%0,%1,%2,%3};"
        : "+f"(d[0]), "+f"(d[1]), "+f"(d[2]), "+f"(d[3])
        : "r"(a[0]), "r"(a[1]), "r"(a[2]), "r"(a[3]), "r"(b[0]), "r"(b[1]));
}

__device__ __forceinline__ void split_f16(float v, __half& hi, __half& lo) {
    hi = __float2half(v);
    lo = __float2half(v - __half2float(hi));
}

// ---------------- graph prep ----------------
__global__ void k_prep_zero() {
    int i = blockIdx.x * blockDim.x + threadIdx.x;
    if (i < NNODES) { g_deg[i] = 0.f; g_count[i] = 0; }
}
__global__ void k_prep_edges(const int* __restrict__ src, const int* __restrict__ dst,
                             const float* __restrict__ ew) {
    int e = blockIdx.x * blockDim.x + threadIdx.x;
    if (e < NEDGES) {
        atomicAdd(&g_deg[dst[e]], ew[e]);
        atomicAdd(&g_count[dst[e]], 1);
    }
}
__global__ void k_prep_node() {
    int i = blockIdx.x * blockDim.x + threadIdx.x;
    if (i < NNODES) {
        float d = g_deg[i] + 1.0f;
        g_dinv[i] = rsqrtf(d);
        g_self[i] = 1.0f / d;
    }
}
__global__ void k_scan() {
    int tid = threadIdx.x;
    int c[16];
    int tot = 0;
#pragma unroll
    for (int j = 0; j < 16; j++) { c[j] = tot; tot += g_count[tid * 16 + j]; }
    __shared__ int s[1024];
    s[tid] = tot;
    __syncthreads();
    int mytot = tot;
    for (int off = 1; off < 1024; off <<= 1) {
        int v = (tid >= off) ? s[tid - off] : 0;
        __syncthreads();
        s[tid] += v;
        __syncthreads();
    }
    int incl = s[tid];
    int excl = incl - mytot;
#pragma unroll
    for (int j = 0; j < 16; j++) {
        int v = excl + c[j];
        g_rowptr[tid * 16 + j] = v;
        g_cursor[tid * 16 + j] = v;
    }
    if (tid == 1023) g_rowptr[NNODES] = incl;
}
__global__ void k_fill(const int* __restrict__ src, const int* __restrict__ dst,
                       const float* __restrict__ ew) {
    int e = blockIdx.x * blockDim.x + threadIdx.x;
    if (e < NEDGES) {
        int s = src[e], d = dst[e];
        float norm = g_dinv[s] * ew[e] * g_dinv[d];
        int p = atomicAdd(&g_cursor[d], 1);
        g_csrc[p] = s;
        g_cw[p] = norm;
    }
}

// ---------------- weight conversion: W [K,N] f32 -> Wt fp16 [Npad,K] ----------------
__global__ void k_wconv(const float* __restrict__ W, __half* __restrict__ Wt,
                        int K, int N) {
    __shared__ float t[32][33];
    int k0 = blockIdx.x * 32, nb0 = blockIdx.y * 32;
    int tx = threadIdx.x, ty = threadIdx.y;
    for (int r = ty; r < 32; r += 8) {
        int nn = nb0 + tx;
        t[r][tx] = (nn < N) ? W[(size_t)(k0 + r) * N + nn] : 0.f;
    }
    __syncthreads();
    for (int r = ty; r < 32; r += 8) {
        int nn = nb0 + r;
        Wt[(size_t)nn * K + k0 + tx] = __float2half(t[tx][r]);
    }
}

// ---------------- aggregation kernels (CSR gather) ----------------
// MODE: 0 = f32 input (layer 1, x); 1 = split fp16 input;
//       2 = post (input split, add bias, relu) [layer 4]
template <int MODE>
__global__ void k_agg(const float* __restrict__ xf,
                      const __half* __restrict__ inHi, const __half* __restrict__ inLo,
                      const float* __restrict__ bias,
                      __half* __restrict__ outHi, __half* __restrict__ outLo, int F) {
    int n  = blockIdx.y;
    int f4 = blockIdx.x * blockDim.x + threadIdx.x;
    int F4 = F >> 2;
    if (f4 >= F4) return;

    auto loadrow = [&](int row, float4& v) {
        if (MODE == 0) {
            v = ((const float4*)(xf + (size_t)row * F))[f4];
        } else {
            const __half2* ph = ((const __half2*)(inHi + (size_t)row * F)) + f4 * 2;
            const __half2* pl = ((const __half2*)(inLo + (size_t)row * F)) + f4 * 2;
            float2 h0 = __half22float2(ph[0]);
            float2 h1 = __half22float2(ph[1]);
            float2 l0 = __half22float2(pl[0]);
            float2 l1 = __half22float2(pl[1]);
            v.x = h0.x + l0.x; v.y = h0.y + l0.y;
            v.z = h1.x + l1.x; v.w = h1.y + l1.y;
        }
    };

    float4 hv; loadrow(n, hv);
    float sc = g_self[n];
    float4 acc = make_float4(sc * hv.x, sc * hv.y, sc * hv.z, sc * hv.w);
    int beg = g_rowptr[n], end = g_rowptr[n + 1];
    for (int j = beg; j < end; j++) {
        int   s = g_csrc[j];
        float w = g_cw[j];
        float4 sv; loadrow(s, sv);
        acc.x += w * sv.x; acc.y += w * sv.y;
        acc.z += w * sv.z; acc.w += w * sv.w;
    }
    if (MODE == 2) {
        float4 bb = ((const float4*)bias)[f4];
        acc.x = fmaxf(acc.x + bb.x, 0.f);
        acc.y = fmaxf(acc.y + bb.y, 0.f);
        acc.z = fmaxf(acc.z + bb.z, 0.f);
        acc.w = fmaxf(acc.w + bb.w, 0.f);
    }
    __half h0, l0, h1, l1, h2, l2, h3, l3;
    split_f16(acc.x, h0, l0); split_f16(acc.y, h1, l1);
    split_f16(acc.z, h2, l2); split_f16(acc.w, h3, l3);
    __half2* ph = ((__half2*)(outHi + (size_t)n * F)) + f4 * 2;
    __half2* pl = ((__half2*)(outLo + (size_t)n * F)) + f4 * 2;
    ph[0] = __halves2half2(h0, h1);
    ph[1] = __halves2half2(h2, h3);
    pl[0] = __halves2half2(l0, l1);
    pl[1] = __halves2half2(l2, l3);
}

// ---------------- mma.sync fp16 split-A GEMM ----------------
// CTA 128x256, 512 threads (16 warps, warp tile 32x64), BK=32, 4-stage cp.async.
// A [M,K] split fp16 (hi+lo), B = Wt [Npad,K] single fp16.
// C = (Ah + Al) @ B^T : 2 MMA terms.
// Inner loop: per 16-k step, batch all 8 ldmatrix first, then 32-HMMA burst.
#define BM 128
#define BN 256
#define BKC 32
#define LDT 40                          // fp16 elems per row (80 B)
#define A_T (128 * LDT * 2)             // 10240 B
#define B_T (256 * LDT * 2)             // 20480 B
#define STAGE_B (2 * A_T + B_T)         // 40960 B: Ah, Al, B
#define NSTAGE 4
#define GEMM_SMEM (NSTAGE * STAGE_B)    // 163840 B

template <int MODE>
__global__ void __launch_bounds__(512, 1)
k_gemm_mma(const __half* __restrict__ Ah, const __half* __restrict__ Al,
           const __half* __restrict__ Bw,
           __half* __restrict__ OHi, __half* __restrict__ OLo,
           float* __restrict__ Cf, const float* __restrict__ bias,
           int K, int Ncols, int KC) {
    extern __shared__ char smem[];
    uint32_t sb = smem_u32(smem);
    int tid = threadIdx.x;
    int wid = tid >> 5, lane = tid & 31;
    int m0 = blockIdx.y * BM, n0 = blockIdx.x * BN;
    int wm = wid & 3;        // warp m tile (32 rows)
    int wn = wid >> 2;       // warp n tile (64 cols, 0..3)

    const __half* A0h = Ah + (size_t)m0 * K;
    const __half* A0l = Al + (size_t)m0 * K;
    const __half* B0  = Bw + (size_t)n0 * K;

    int lrow = tid >> 2;       // 0..127
    int lg   = tid & 3;        // 16B group
    auto load_chunk = [&](int c, int s) {
        uint32_t tb = sb + s * STAGE_B;
        size_t koff = (size_t)c * BKC;
        uint32_t so = (uint32_t)(lrow * (LDT * 2) + lg * 16);
        size_t go = (size_t)lrow * K + koff + lg * 8;
        cp16(tb + so,       A0h + go);
        cp16(tb + A_T + so, A0l + go);
#pragma unroll
        for (int half = 0; half < 2; half++) {
            int row = lrow + half * 128;
            uint32_t sob = (uint32_t)(row * (LDT * 2) + lg * 16);
            size_t gob = (size_t)row * K + koff + lg * 8;
            cp16(tb + 2 * A_T + sob, B0 + gob);
        }
    };

    int quad = lane >> 3, r = lane & 7;
    uint32_t aOff = (uint32_t)(((wm * 32 + (quad & 1) * 8 + r) * LDT + (quad >> 1) * 8) * 2);
    uint32_t bOff = (uint32_t)(((wn * 64 + (quad >> 1) * 8 + r) * LDT + (quad & 1) * 8) * 2);

    float acc[2][8][4];
#pragma unroll
    for (int i = 0; i < 2; i++)
#pragma unroll
        for (int j = 0; j < 8; j++)
#pragma unroll
            for (int q = 0; q < 4; q++) acc[i][j][q] = 0.f;

    // prologue: fill 3 of 4 stages
    load_chunk(0, 0); cp_commit();
    if (KC > 1) { load_chunk(1, 1); cp_commit(); }
    if (KC > 2) { load_chunk(2, 2); cp_commit(); }

    for (int kc = 0; kc < KC; kc++) {
        int s = kc & 3;
        // groups committed for chunks > kc:
        int after = (kc + 3 < KC ? 3 : KC - 1 - kc) - 0;
        if (after >= 2) cp_wait<2>();
        else if (after == 1) cp_wait<1>();
        else cp_wait<0>();
        __syncthreads();

        uint32_t st = sb + s * STAGE_B;
#pragma unroll
        for (int ks = 0; ks < 2; ks++) {
            uint32_t ko = ks * 32;  // 16 elems * 2B
            // batch all fragment loads
            uint32_t ah[2][4], al[2][4], bf[4][4];
#pragma unroll
            for (int mi = 0; mi < 2; mi++) {
                ldsm4(ah[mi], st + aOff + mi * (16 * LDT * 2) + ko);
                ldsm4(al[mi], st + A_T + aOff + mi * (16 * LDT * 2) + ko);
            }
#pragma unroll
            for (int p = 0; p < 4; p++)
                ldsm4(bf[p], st + 2 * A_T + bOff + p * (16 * LDT * 2) + ko);
            // 32-HMMA burst
#pragma unroll
            for (int p = 0; p < 4; p++)
#pragma unroll
                for (int mi = 0; mi < 2; mi++)
#pragma unroll
                    for (int h = 0; h < 2; h++) {
                        int ni = 2 * p + h;
                        mma16816(acc[mi][ni], ah[mi], &bf[p][h * 2]);
                        mma16816(acc[mi][ni], al[mi], &bf[p][h * 2]);
                    }
        }

        if (kc + 3 < KC) {
            load_chunk(kc + 3, (kc + 3) & 3);
            cp_commit();
        }
        __syncthreads();
    }

    // epilogue
    int cr = lane >> 2, cc = (lane & 3) * 2;
#pragma unroll
    for (int mi = 0; mi < 2; mi++) {
#pragma unroll
        for (int ni = 0; ni < 8; ni++) {
            int n = n0 + wn * 64 + ni * 8 + cc;
#pragma unroll
            for (int hh = 0; hh < 2; hh++) {
                int m = m0 + wm * 32 + mi * 16 + cr + hh * 8;
                float v0 = acc[mi][ni][hh * 2 + 0];
                float v1 = acc[mi][ni][hh * 2 + 1];
                if (MODE == 2) {
                    if (n < Ncols)     Cf[(size_t)m * Ncols + n]     = v0 + bias[n];
                    if (n + 1 < Ncols) Cf[(size_t)m * Ncols + n + 1] = v1 + bias[n + 1];
                } else {
                    if (MODE == 0) {
                        v0 = fmaxf(v0 + bias[n], 0.f);
                        v1 = fmaxf(v1 + bias[n + 1], 0.f);
                    }
                    __half h0, l0, h1, l1;
                    split_f16(v0, h0, l0);
                    split_f16(v1, h1, l1);
                    *(__half2*)(OHi + (size_t)m * Ncols + n) = __halves2half2(h0, h1);
                    *(__half2*)(OLo + (size_t)m * Ncols + n) = __halves2half2(l0, l1);
                }
            }
        }
    }
}

// ---------------- host orchestration ----------------
static inline void launch_gemm(int mode,
                               const __half* Ah, const __half* Al, const __half* Bw,
                               __half* OHi, __half* OLo, float* Cf, const float* bias,
                               int K, int Ncols, int Npad) {
    dim3 grid(Npad / BN, NNODES / BM);
    if (mode == 0) {
        cudaFuncSetAttribute(k_gemm_mma<0>, cudaFuncAttributeMaxDynamicSharedMemorySize, GEMM_SMEM);
        k_gemm_mma<0><<<grid, 512, GEMM_SMEM>>>(Ah, Al, Bw, OHi, OLo, Cf, bias, K, Ncols, K / BKC);
    } else if (mode == 1) {
        cudaFuncSetAttribute(k_gemm_mma<1>, cudaFuncAttributeMaxDynamicSharedMemorySize, GEMM_SMEM);
        k_gemm_mma<1><<<grid, 512, GEMM_SMEM>>>(Ah, Al, Bw, OHi, OLo, Cf, bias, K, Ncols, K / BKC);
    } else {
        cudaFuncSetAttribute(k_gemm_mma<2>, cudaFuncAttributeMaxDynamicSharedMemorySize, GEMM_SMEM);
        k_gemm_mma<2><<<grid, 512, GEMM_SMEM>>>(Ah, Al, Bw, OHi, OLo, Cf, bias, K, Ncols, K / BKC);
    }
}

static inline void launch_wconv(const float* W, __half* Wt, int K, int N, int Npad) {
    dim3 grid(K / 32, Npad / 32);
    k_wconv<<<grid, dim3(32, 8)>>>(W, Wt, K, N);
}

extern "C" void kernel_launch(void* const* d_in, const int* in_sizes, int n_in,
                              void* d_out, int out_size) {
    const float* x    = (const float*)d_in[0];
    const int*   esrc = (const int*)d_in[1];
    const int*   edst = (const int*)d_in[2];
    const float* ew   = (const float*)d_in[3];
    const float* W1 = (const float*)d_in[4];
    const float* b1 = (const float*)d_in[5];
    const float* W2 = (const float*)d_in[6];
    const float* b2 = (const float*)d_in[7];
    const float* W3 = (const float*)d_in[8];
    const float* b3 = (const float*)d_in[9];
    const float* W4 = (const float*)d_in[10];
    const float* b4 = (const float*)d_in[11];
    const float* Wout = (const float*)d_in[12];
    const float* bout = (const float*)d_in[13];
    float* out = (float*)d_out;

    __half *ahi, *alo, *ghi, *glo, *wt;
    cudaGetSymbolAddress((void**)&ahi, g_ahi);
    cudaGetSymbolAddress((void**)&alo, g_alo);
    cudaGetSymbolAddress((void**)&ghi, g_ghi);
    cudaGetSymbolAddress((void**)&glo, g_glo);
    cudaGetSymbolAddress((void**)&wt, g_wt);

    // graph prep
    k_prep_zero<<<NNODES / 256, 256>>>();
    k_prep_edges<<<NEDGES / 256, 256>>>(esrc, edst, ew);
    k_prep_node<<<NNODES / 256, 256>>>();
    k_scan<<<1, 1024>>>();
    k_fill<<<NEDGES / 256, 256>>>(esrc, edst, ew);

    auto agg_grid = [](int F) { return dim3(((F >> 2) + 255) / 256, NNODES); };

    // L1: g = agg(x) [512]; a = relu(g W1 + b1) [1024]
    k_agg<0><<<agg_grid(512), 256>>>(x, nullptr, nullptr, nullptr, ghi, glo, 512);
    launch_wconv(W1, wt, 512, 1024, 1024);
    launch_gemm(0, ghi, glo, wt, ahi, alo, nullptr, b1, 512, 1024, 1024);

    // L2: g = agg(a) [1024]; a = relu(g W2 + b2) [2048]
    k_agg<1><<<agg_grid(1024), 256>>>(nullptr, ahi, alo, nullptr, ghi, glo, 1024);
    launch_wconv(W2, wt, 1024, 2048, 2048);
    launch_gemm(0, ghi, glo, wt, ahi, alo, nullptr, b2, 1024, 2048, 2048);

    // L3: g = agg(a) [2048]; a = relu(g W3 + b3) [4096]
    k_agg<1><<<agg_grid(2048), 256>>>(nullptr, ahi, alo, nullptr, ghi, glo, 2048);
    launch_wconv(W3, wt, 2048, 4096, 4096);
    launch_gemm(0, ghi, glo, wt, ahi, alo, nullptr, b3, 2048, 4096, 4096);

    // L4 (agg after): h = a W4 [2048]; a = relu(agg(h) + b4)
    launch_wconv(W4, wt, 4096, 2048, 2048);
    launch_gemm(1, ahi, alo, wt, ghi, glo, nullptr, nullptr, 4096, 2048, 2048);
    k_agg<2><<<agg_grid(2048), 256>>>(nullptr, ghi, glo, b4, ahi, alo, 2048);

    // L5 (output): out = a Wout + bout [1000]
    launch_wconv(Wout, wt, 2048, 1000, 1024);
    launch_gemm(2, ahi, alo, wt, nullptr, nullptr, out, bout, 2048, 1000, 1024);
}

// round 10
// speedup vs baseline: 6.2617x; 1.5608x over previous
#include <cuda_runtime.h>
#include <cuda_fp16.h>
#include <cstdint>

#define NNODES 16384
#define NEDGES 65536
#define MAXF   4096

// ---------------- scratch (device globals; no allocation) ----------------
__device__ __half g_a[(size_t)NNODES * MAXF];     // activation buffer A (fp16)
__device__ __half g_g[(size_t)NNODES * MAXF];     // buffer B (fp16)
__device__ __half g_wt[(size_t)4096 * 4096];      // transposed weights fp16 [Npad,K]
__device__ float g_deg[NNODES];
__device__ float g_dinv[NNODES];
__device__ float g_self[NNODES];
__device__ int   g_count[NNODES];
__device__ int   g_rowptr[NNODES + 1];
__device__ int   g_cursor[NNODES];
__device__ int   g_csrc[NEDGES];
__device__ float g_cw[NEDGES];

// ---------------- PTX helpers (baseline PTX only) ----------------
__device__ __forceinline__ uint32_t smem_u32(const void* p) {
    uint32_t a;
    asm("{ .reg .u64 t; cvta.to.shared.u64 t, %1; cvt.u32.u64 %0, t; }" : "=r"(a) : "l"(p));
    return a;
}
__device__ __forceinline__ void cp16(uint32_t s, const void* g) {
    asm volatile("cp.async.cg.shared.global [%0], [%1], 16;" :: "r"(s), "l"(g));
}
__device__ __forceinline__ void cp_commit() { asm volatile("cp.async.commit_group;" ::: "memory"); }
template <int N>
__device__ __forceinline__ void cp_wait() { asm volatile("cp.async.wait_group %0;" :: "n"(N) : "memory"); }

__device__ __forceinline__ void ldsm4(uint32_t* r, uint32_t addr) {
    asm volatile("ldmatrix.sync.aligned.m8n8.x4.shared.b16 {%0,%1,%2,%3}, [%4];"
                 : "=r"(r[0]), "=r"(r[1]), "=r"(r[2]), "=r"(r[3]) : "r"(addr));
}
__device__ __forceinline__ void mma16816(float* d, const uint32_t* a, const uint32_t* b) {
    asm volatile(
        "mma.sync.aligned.m16n8k16.row.col.f32.f16.f16.f32 "
        "{%0,%1,%2,%3}, {%4,%5,%6,%7}, {%8,%9}, {%0,%1,%2,%3};"
        : "+f"(d[0]), "+f"(d[1]), "+f"(d[2]), "+f"(d[3])
        : "r"(a[0]), "r"(a[1]), "r"(a[2]), "r"(a[3]), "r"(b[0]), "r"(b[1]));
}

// ---------------- graph prep ----------------
__global__ void k_prep_zero() {
    int i = blockIdx.x * blockDim.x + threadIdx.x;
    if (i < NNODES) { g_deg[i] = 0.f; g_count[i] = 0; }
}
__global__ void k_prep_edges(const int* __restrict__ src, const int* __restrict__ dst,
                             const float* __restrict__ ew) {
    int e = blockIdx.x * blockDim.x + threadIdx.x;
    if (e < NEDGES) {
        atomicAdd(&g_deg[dst[e]], ew[e]);
        atomicAdd(&g_count[dst[e]], 1);
    }
}
__global__ void k_prep_node() {
    int i = blockIdx.x * blockDim.x + threadIdx.x;
    if (i < NNODES) {
        float d = g_deg[i] + 1.0f;
        g_dinv[i] = rsqrtf(d);
        g_self[i] = 1.0f / d;
    }
}
__global__ void k_scan() {
    int tid = threadIdx.x;
    int c[16];
    int tot = 0;
#pragma unroll
    for (int j = 0; j < 16; j++) { c[j] = tot; tot += g_count[tid * 16 + j]; }
    __shared__ int s[1024];
    s[tid] = tot;
    __syncthreads();
    int mytot = tot;
    for (int off = 1; off < 1024; off <<= 1) {
        int v = (tid >= off) ? s[tid - off] : 0;
        __syncthreads();
        s[tid] += v;
        __syncthreads();
    }
    int incl = s[tid];
    int excl = incl - mytot;
#pragma unroll
    for (int j = 0; j < 16; j++) {
        int v = excl + c[j];
        g_rowptr[tid * 16 + j] = v;
        g_cursor[tid * 16 + j] = v;
    }
    if (tid == 1023) g_rowptr[NNODES] = incl;
}
__global__ void k_fill(const int* __restrict__ src, const int* __restrict__ dst,
                       const float* __restrict__ ew) {
    int e = blockIdx.x * blockDim.x + threadIdx.x;
    if (e < NEDGES) {
        int s = src[e], d = dst[e];
        float norm = g_dinv[s] * ew[e] * g_dinv[d];
        int p = atomicAdd(&g_cursor[d], 1);
        g_csrc[p] = s;
        g_cw[p] = norm;
    }
}

// ---------------- weight conversion: W [K,N] f32 -> Wt fp16 [Npad,K] ----------------
__global__ void k_wconv(const float* __restrict__ W, __half* __restrict__ Wt,
                        int K, int N) {
    __shared__ float t[32][33];
    int k0 = blockIdx.x * 32, nb0 = blockIdx.y * 32;
    int tx = threadIdx.x, ty = threadIdx.y;
    for (int r = ty; r < 32; r += 8) {
        int nn = nb0 + tx;
        t[r][tx] = (nn < N) ? W[(size_t)(k0 + r) * N + nn] : 0.f;
    }
    __syncthreads();
    for (int r = ty; r < 32; r += 8) {
        int nn = nb0 + r;
        Wt[(size_t)nn * K + k0 + tx] = __float2half(t[tx][r]);
    }
}

// ---------------- aggregation kernels (CSR gather) ----------------
// MODE: 0 = f32 input (layer 1, x); 1 = fp16 input;
//       2 = post (fp16 input, add bias, relu) [layer 4]
template <int MODE>
__global__ void k_agg(const float* __restrict__ xf, const __half* __restrict__ inA,
                      const float* __restrict__ bias,
                      __half* __restrict__ outA, int F) {
    int n  = blockIdx.y;
    int f4 = blockIdx.x * blockDim.x + threadIdx.x;
    int F4 = F >> 2;
    if (f4 >= F4) return;

    auto loadrow = [&](int row, float4& v) {
        if (MODE == 0) {
            v = ((const float4*)(xf + (size_t)row * F))[f4];
        } else {
            const __half2* ph = ((const __half2*)(inA + (size_t)row * F)) + f4 * 2;
            float2 h0 = __half22float2(ph[0]);
            float2 h1 = __half22float2(ph[1]);
            v.x = h0.x; v.y = h0.y; v.z = h1.x; v.w = h1.y;
        }
    };

    float4 hv; loadrow(n, hv);
    float sc = g_self[n];
    float4 acc = make_float4(sc * hv.x, sc * hv.y, sc * hv.z, sc * hv.w);
    int beg = g_rowptr[n], end = g_rowptr[n + 1];
    for (int j = beg; j < end; j++) {
        int   s = g_csrc[j];
        float w = g_cw[j];
        float4 sv; loadrow(s, sv);
        acc.x += w * sv.x; acc.y += w * sv.y;
        acc.z += w * sv.z; acc.w += w * sv.w;
    }
    if (MODE == 2) {
        float4 bb = ((const float4*)bias)[f4];
        acc.x = fmaxf(acc.x + bb.x, 0.f);
        acc.y = fmaxf(acc.y + bb.y, 0.f);
        acc.z = fmaxf(acc.z + bb.z, 0.f);
        acc.w = fmaxf(acc.w + bb.w, 0.f);
    }
    __half2* ph = ((__half2*)(outA + (size_t)n * F)) + f4 * 2;
    ph[0] = __floats2half2_rn(acc.x, acc.y);
    ph[1] = __floats2half2_rn(acc.z, acc.w);
}

// ---------------- mma.sync fp16 GEMM (single term) ----------------
// CTA 128x256, 512 threads (16 warps, warp tile 32x64), BK=32, 4-stage cp.async.
// A [M,K] fp16, B = Wt [Npad,K] fp16.  C = A @ B^T.
#define BM 128
#define BN 256
#define BKC 32
#define LDT 40                          // fp16 elems per row (80 B)
#define A_T (128 * LDT * 2)             // 10240 B
#define B_T (256 * LDT * 2)             // 20480 B
#define STAGE_B (A_T + B_T)             // 30720 B
#define NSTAGE 4
#define GEMM_SMEM (NSTAGE * STAGE_B)    // 122880 B

template <int MODE>
__global__ void __launch_bounds__(512, 1)
k_gemm_mma(const __half* __restrict__ Aa, const __half* __restrict__ Bw,
           __half* __restrict__ Oh, float* __restrict__ Cf,
           const float* __restrict__ bias,
           int K, int Ncols, int KC) {
    extern __shared__ char smem[];
    uint32_t sb = smem_u32(smem);
    int tid = threadIdx.x;
    int wid = tid >> 5, lane = tid & 31;
    int m0 = blockIdx.y * BM, n0 = blockIdx.x * BN;
    int wm = wid & 3;        // warp m tile (32 rows)
    int wn = wid >> 2;       // warp n tile (64 cols, 0..3)

    const __half* A0 = Aa + (size_t)m0 * K;
    const __half* B0 = Bw + (size_t)n0 * K;

    int lrow = tid >> 2;       // 0..127
    int lg   = tid & 3;        // 16B group
    auto load_chunk = [&](int c, int s) {
        uint32_t tb = sb + s * STAGE_B;
        size_t koff = (size_t)c * BKC;
        uint32_t so = (uint32_t)(lrow * (LDT * 2) + lg * 16);
        size_t go = (size_t)lrow * K + koff + lg * 8;
        cp16(tb + so, A0 + go);
#pragma unroll
        for (int half = 0; half < 2; half++) {
            int row = lrow + half * 128;
            uint32_t sob = (uint32_t)(row * (LDT * 2) + lg * 16);
            size_t gob = (size_t)row * K + koff + lg * 8;
            cp16(tb + A_T + sob, B0 + gob);
        }
    };

    int quad = lane >> 3, r = lane & 7;
    uint32_t aOff = (uint32_t)(((wm * 32 + (quad & 1) * 8 + r) * LDT + (quad >> 1) * 8) * 2);
    uint32_t bOff = (uint32_t)(((wn * 64 + (quad >> 1) * 8 + r) * LDT + (quad & 1) * 8) * 2);

    float acc[2][8][4];
#pragma unroll
    for (int i = 0; i < 2; i++)
#pragma unroll
        for (int j = 0; j < 8; j++)
#pragma unroll
            for (int q = 0; q < 4; q++) acc[i][j][q] = 0.f;

    // prologue: fill 3 of 4 stages
    load_chunk(0, 0); cp_commit();
    if (KC > 1) { load_chunk(1, 1); cp_commit(); }
    if (KC > 2) { load_chunk(2, 2); cp_commit(); }

    for (int kc = 0; kc < KC; kc++) {
        int s = kc & 3;
        int after = (kc + 3 < KC ? 3 : KC - 1 - kc);
        if (after >= 2) cp_wait<2>();
        else if (after == 1) cp_wait<1>();
        else cp_wait<0>();
        __syncthreads();

        uint32_t st = sb + s * STAGE_B;
#pragma unroll
        for (int ks = 0; ks < 2; ks++) {
            uint32_t ko = ks * 32;  // 16 elems * 2B
            uint32_t af[2][4], bf[4][4];
#pragma unroll
            for (int mi = 0; mi < 2; mi++)
                ldsm4(af[mi], st + aOff + mi * (16 * LDT * 2) + ko);
#pragma unroll
            for (int p = 0; p < 4; p++)
                ldsm4(bf[p], st + A_T + bOff + p * (16 * LDT * 2) + ko);
#pragma unroll
            for (int p = 0; p < 4; p++)
#pragma unroll
                for (int mi = 0; mi < 2; mi++)
#pragma unroll
                    for (int h = 0; h < 2; h++)
                        mma16816(acc[mi][2 * p + h], af[mi], &bf[p][h * 2]);
        }

        if (kc + 3 < KC) {
            load_chunk(kc + 3, (kc + 3) & 3);
            cp_commit();
        }
        __syncthreads();
    }

    // epilogue
    int cr = lane >> 2, cc = (lane & 3) * 2;
#pragma unroll
    for (int mi = 0; mi < 2; mi++) {
#pragma unroll
        for (int ni = 0; ni < 8; ni++) {
            int n = n0 + wn * 64 + ni * 8 + cc;
#pragma unroll
            for (int hh = 0; hh < 2; hh++) {
                int m = m0 + wm * 32 + mi * 16 + cr + hh * 8;
                float v0 = acc[mi][ni][hh * 2 + 0];
                float v1 = acc[mi][ni][hh * 2 + 1];
                if (MODE == 2) {
                    if (n < Ncols)     Cf[(size_t)m * Ncols + n]     = v0 + bias[n];
                    if (n + 1 < Ncols) Cf[(size_t)m * Ncols + n + 1] = v1 + bias[n + 1];
                } else {
                    if (MODE == 0) {
                        v0 = fmaxf(v0 + bias[n], 0.f);
                        v1 = fmaxf(v1 + bias[n + 1], 0.f);
                    }
                    *(__half2*)(Oh + (size_t)m * Ncols + n) = __floats2half2_rn(v0, v1);
                }
            }
        }
    }
}

// ---------------- host orchestration ----------------
static inline void launch_gemm(int mode,
                               const __half* Aa, const __half* Bw,
                               __half* Oh, float* Cf, const float* bias,
                               int K, int Ncols, int Npad) {
    dim3 grid(Npad / BN, NNODES / BM);
    if (mode == 0) {
        cudaFuncSetAttribute(k_gemm_mma<0>, cudaFuncAttributeMaxDynamicSharedMemorySize, GEMM_SMEM);
        k_gemm_mma<0><<<grid, 512, GEMM_SMEM>>>(Aa, Bw, Oh, Cf, bias, K, Ncols, K / BKC);
    } else if (mode == 1) {
        cudaFuncSetAttribute(k_gemm_mma<1>, cudaFuncAttributeMaxDynamicSharedMemorySize, GEMM_SMEM);
        k_gemm_mma<1><<<grid, 512, GEMM_SMEM>>>(Aa, Bw, Oh, Cf, bias, K, Ncols, K / BKC);
    } else {
        cudaFuncSetAttribute(k_gemm_mma<2>, cudaFuncAttributeMaxDynamicSharedMemorySize, GEMM_SMEM);
        k_gemm_mma<2><<<grid, 512, GEMM_SMEM>>>(Aa, Bw, Oh, Cf, bias, K, Ncols, K / BKC);
    }
}

static inline void launch_wconv(const float* W, __half* Wt, int K, int N, int Npad) {
    dim3 grid(K / 32, Npad / 32);
    k_wconv<<<grid, dim3(32, 8)>>>(W, Wt, K, N);
}

extern "C" void kernel_launch(void* const* d_in, const int* in_sizes, int n_in,
                              void* d_out, int out_size) {
    const float* x    = (const float*)d_in[0];
    const int*   esrc = (const int*)d_in[1];
    const int*   edst = (const int*)d_in[2];
    const float* ew   = (const float*)d_in[3];
    const float* W1 = (const float*)d_in[4];
    const float* b1 = (const float*)d_in[5];
    const float* W2 = (const float*)d_in[6];
    const float* b2 = (const float*)d_in[7];
    const float* W3 = (const float*)d_in[8];
    const float* b3 = (const float*)d_in[9];
    const float* W4 = (const float*)d_in[10];
    const float* b4 = (const float*)d_in[11];
    const float* Wout = (const float*)d_in[12];
    const float* bout = (const float*)d_in[13];
    float* out = (float*)d_out;

    __half *abuf, *gbuf, *wt;
    cudaGetSymbolAddress((void**)&abuf, g_a);
    cudaGetSymbolAddress((void**)&gbuf, g_g);
    cudaGetSymbolAddress((void**)&wt, g_wt);

    // graph prep
    k_prep_zero<<<NNODES / 256, 256>>>();
    k_prep_edges<<<NEDGES / 256, 256>>>(esrc, edst, ew);
    k_prep_node<<<NNODES / 256, 256>>>();
    k_scan<<<1, 1024>>>();
    k_fill<<<NEDGES / 256, 256>>>(esrc, edst, ew);

    auto agg_grid = [](int F) { return dim3(((F >> 2) + 255) / 256, NNODES); };

    // L1: g = agg(x) [512]; a = relu(g W1 + b1) [1024]
    k_agg<0><<<agg_grid(512), 256>>>(x, nullptr, nullptr, gbuf, 512);
    launch_wconv(W1, wt, 512, 1024, 1024);
    launch_gemm(0, gbuf, wt, abuf, nullptr, b1, 512, 1024, 1024);

    // L2: g = agg(a) [1024]; a = relu(g W2 + b2) [2048]
    k_agg<1><<<agg_grid(1024), 256>>>(nullptr, abuf, nullptr, gbuf, 1024);
    launch_wconv(W2, wt, 1024, 2048, 2048);
    launch_gemm(0, gbuf, wt, abuf, nullptr, b2, 1024, 2048, 2048);

    // L3: g = agg(a) [2048]; a = relu(g W3 + b3) [4096]
    k_agg<1><<<agg_grid(2048), 256>>>(nullptr, abuf, nullptr, gbuf, 2048);
    launch_wconv(W3, wt, 2048, 4096, 4096);
    launch_gemm(0, gbuf, wt, abuf, nullptr, b3, 2048, 4096, 4096);

    // L4 (agg after): h = a W4 [2048]; a = relu(agg(h) + b4)
    launch_wconv(W4, wt, 4096, 2048, 2048);
    launch_gemm(1, abuf, wt, gbuf, nullptr, nullptr, 4096, 2048, 2048);
    k_agg<2><<<agg_grid(2048), 256>>>(nullptr, gbuf, b4, abuf, 2048);

    // L5 (output): out = a Wout + bout [1000]
    launch_wconv(Wout, wt, 2048, 1000, 1024);
    launch_gemm(2, abuf, wt, nullptr, out, bout, 2048, 1000, 1024);
}